// round 15
// baseline (speedup 1.0000x reference)
#include <cuda_runtime.h>
#include <cuda_bf16.h>
#include <cuda_fp16.h>
#include <math.h>
#include <stdint.h>

// ---------------- problem constants ----------------
#define B_   2
#define S_   2048
#define HID  2048
#define HKq  16
#define HVv  32
#define DKd  128
#define DVd  128
#define KC   4
#define CHUNK 64
#define NCH  (S_/CHUNK)          // 32
#define KEY_DIM 2048
#define VALUE_DIM 4096
#define CONV_DIM 8192
#define QKVZ_N 12288
#define BSz  (B_*S_)             // 4096
#define QSCALE 0.08838834764831845f   // DK^-0.5
#define SW 132
#define STF 132
#define SH6 136
#define SH7 72

// ---------------- scratch (static device memory; no allocations) ------------
__device__ float g_qkvz[(size_t)BSz*QKVZ_N];
__device__ float g_ba[(size_t)BSz*64];
__device__ float g_q[(size_t)B_*HKq*S_*DKd];
__device__ float g_k[(size_t)B_*HKq*S_*DKd];
__device__ float g_v[(size_t)B_*HVv*S_*DVd];
__device__ float g_g[(size_t)B_*HVv*S_];
__device__ float g_beta[(size_t)B_*HVv*S_];
__device__ float g_gc[(size_t)B_*HVv*S_];
__device__ float g_vadj[(size_t)B_*HVv*S_*DVd];
__device__ float g_kcd[(size_t)B_*HVv*S_*DKd];
__device__ float g_attn[(size_t)B_*HVv*S_*CHUNK];
__device__ float g_o[(size_t)BSz*VALUE_DIM];

__device__ __half g_p [(size_t)8388608];    // A1 (hidden) / B2t (Wout^T)
__device__ __half g_r [(size_t)25165824];   // B1t (Wqkvz^T) ; later A2
__device__ __half g_wba[(size_t)64*2048];   // W_ba^T fp16

__device__ __forceinline__ uint32_t smem_u32(const void* p) {
    uint32_t a;
    asm("{ .reg .u64 t; cvta.to.shared.u64 t, %1; cvt.u32.u64 %0, t; }" : "=r"(a) : "l"(p));
    return a;
}

// ---------------- fp32 -> fp16 (elementwise, float4) ----------------
__global__ void cvt_h(const float* __restrict__ X, __half* __restrict__ H) {
    size_t i = ((size_t)blockIdx.x * 256 + threadIdx.x) * 4;
    float4 v = *(const float4*)&X[i];
    __half2 h0 = __floats2half2_rn(v.x, v.y);
    __half2 h1 = __floats2half2_rn(v.z, v.w);
    uint2 hv;
    hv.x = *(uint32_t*)&h0; hv.y = *(uint32_t*)&h1;
    *(uint2*)&H[i] = hv;
}

// ---------------- fp32 [K,N] -> fp16 [N,K] transpose ----------------
__global__ void cvt_T(const float* __restrict__ W, __half* __restrict__ Ht, int K, int N) {
    __shared__ float tile[32][33];
    int n0 = blockIdx.x * 32, k0 = blockIdx.y * 32;
    int tx = threadIdx.x, ty = threadIdx.y;
#pragma unroll
    for (int j = 0; j < 32; j += 8)
        tile[ty + j][tx] = W[(size_t)(k0 + ty + j) * N + n0 + tx];
    __syncthreads();
#pragma unroll
    for (int j = 0; j < 32; j += 8)
        Ht[(size_t)(n0 + ty + j) * K + k0 + tx] = __float2half_rn(tile[tx][ty + j]);
}

// ============ fp16 HMMA GEMM: C[M,N] = A[M,K] @ Bt[N,K]^T (fp32 accum) ============
// 4 stages, 2 ktiles per barrier pair (halved syncs, longer mma runs).
#define PSH 40
#define TEN2 (128*PSH)
#define STG1 (2*TEN2)
#define NSTG 4

__device__ __forceinline__ void mma_f16(float* c, const uint32_t* a, const uint32_t* b) {
    asm volatile("mma.sync.aligned.m16n8k16.row.col.f32.f16.f16.f32 "
                 "{%0,%1,%2,%3}, {%4,%5,%6,%7}, {%8,%9}, {%0,%1,%2,%3};"
                 : "+f"(c[0]), "+f"(c[1]), "+f"(c[2]), "+f"(c[3])
                 : "r"(a[0]), "r"(a[1]), "r"(a[2]), "r"(a[3]), "r"(b[0]), "r"(b[1]));
}
__device__ __forceinline__ void ldmx4(uint32_t* r, uint32_t addr) {
    asm volatile("ldmatrix.sync.aligned.m8n8.x4.shared.b16 {%0,%1,%2,%3}, [%4];"
                 : "=r"(r[0]), "=r"(r[1]), "=r"(r[2]), "=r"(r[3]) : "r"(addr));
}

__device__ __forceinline__ void stage_load(uint32_t sbase_b, int stage,
    const __half* a0, const __half* b0, int K, int kt, int tid)
{
    const __half* gp[2] = {a0, b0};
    uint32_t st_b = sbase_b + (uint32_t)stage * (STG1 * 2);
#pragma unroll
    for (int t = 0; t < 2; t++) {
        uint32_t tb = st_b + (uint32_t)t * (TEN2 * 2);
#pragma unroll
        for (int j = 0; j < 2; j++) {
            int idx = j * 256 + tid;
            int row = idx >> 2, c16 = idx & 3;
            uint32_t sa = tb + (uint32_t)(row * (PSH*2) + c16 * 16);
            const void* ga = gp[t] + (size_t)row * K + (size_t)kt * 32 + c16 * 8;
            asm volatile("cp.async.cg.shared.global [%0], [%1], 16;" :: "r"(sa), "l"(ga));
        }
    }
    asm volatile("cp.async.commit_group;" ::: "memory");
}

__global__ void __launch_bounds__(256, 2) mmgemm(
    const __half* __restrict__ Ah, const __half* __restrict__ Bh,
    float* __restrict__ C, int M, int N, int K)
{
    extern __shared__ __half smem[];
    uint32_t sbase = smem_u32(smem);
    int tid = threadIdx.x, lane = tid & 31, wid = tid >> 5;
    int warpM = wid >> 2, warpN = wid & 3;
    int bm = blockIdx.x, bn = blockIdx.y;
    const int T = K >> 5;                      // T divisible by 4 for all our shapes

    const __half* a0 = Ah + (size_t)bm * 128 * K;
    const __half* b0 = Bh + (size_t)bn * 128 * K;

    int g = lane >> 3, lr = lane & 7;
    uint32_t aoff = (uint32_t)((warpM*64 + (g&1)*8 + lr) * PSH + (g>>1)*8);
    uint32_t boff = (uint32_t)((warpN*32 + (g>>1)*8 + lr) * PSH + (g&1)*8);

    float acc[4][4][4];
#pragma unroll
    for (int i = 0; i < 4; i++)
#pragma unroll
        for (int j = 0; j < 4; j++)
#pragma unroll
            for (int r = 0; r < 4; r++) acc[i][j][r] = 0.f;

    stage_load(sbase, 0, a0, b0, K, 0, tid);
    stage_load(sbase, 1, a0, b0, K, 1, tid);
    stage_load(sbase, 2, a0, b0, K, 2, tid);
    stage_load(sbase, 3, a0, b0, K, 3, tid);

    // compute one ready stage (2 k-slices of 16)
    auto compute_stage = [&](int stg) {
        uint32_t st = sbase + (uint32_t)stg * (STG1 * 2);
        uint32_t sA = st, sB = st + TEN2*2;
#pragma unroll
        for (int ks = 0; ks < 2; ks++) {
            int kk = ks * 16;
            uint32_t ah[4][4], bh[4][2];
#pragma unroll
            for (int mi = 0; mi < 4; mi++)
                ldmx4(ah[mi], sA + (aoff + mi*16*PSH + kk) * 2);
#pragma unroll
            for (int p = 0; p < 2; p++) {
                uint32_t rh[4];
                ldmx4(rh, sB + (boff + p*16*PSH + kk) * 2);
                bh[2*p][0] = rh[0]; bh[2*p][1] = rh[1];
                bh[2*p+1][0] = rh[2]; bh[2*p+1][1] = rh[3];
            }
#pragma unroll
            for (int mi = 0; mi < 4; mi++)
#pragma unroll
                for (int ni = 0; ni < 4; ni++)
                    mma_f16(acc[mi][ni], ah[mi], bh[ni]);
        }
    };

    for (int kt = 0; kt < T; kt += 2) {
        if (kt + 2 < T) asm volatile("cp.async.wait_group 2;" ::: "memory");
        else            asm volatile("cp.async.wait_group 0;" ::: "memory");
        __syncthreads();
        int s0 = kt & 3, s1 = (kt + 1) & 3;
        compute_stage(s0);
        compute_stage(s1);
        __syncthreads();
        if (kt + 4 < T) {
            stage_load(sbase, s0, a0, b0, K, kt + 4, tid);
            stage_load(sbase, s1, a0, b0, K, kt + 5, tid);
        }
    }

    int rr = lane >> 2, cc = (lane & 3) * 2;
#pragma unroll
    for (int mi = 0; mi < 4; mi++) {
        int row0 = bm * 128 + warpM * 64 + mi * 16 + rr;
#pragma unroll
        for (int ni = 0; ni < 4; ni++) {
            int col = bn * 128 + warpN * 32 + ni * 8 + cc;
            float2 v0 = make_float2(acc[mi][ni][0], acc[mi][ni][1]);
            float2 v1 = make_float2(acc[mi][ni][2], acc[mi][ni][3]);
            *(float2*)&C[(size_t)row0 * N + col]       = v0;
            *(float2*)&C[(size_t)(row0 + 8) * N + col] = v1;
        }
    }
}

// ------------- BA projection, HMMA: g_ba[BSz,64] = hidden_fp16 @ Wba^T -------------
__global__ void __launch_bounds__(256) gemm_ba_h(const __half* __restrict__ A) {
    __shared__ __half As[2][32*SH7];
    __shared__ __half Bs[2][64*SH7];
    int tid = threadIdx.x, lane = tid & 31, wid = tid >> 5;
    int bm = blockIdx.x;
    int wm = wid >> 2, wn = wid & 3;
    int g = lane >> 3, lr = lane & 7;
    const __half* Ab = A + (size_t)bm * 32 * 2048;

    uint32_t aoff = (uint32_t)((wm*16 + (g&1)*8 + lr) * SH7 + (g>>1)*8);
    uint32_t boff = (uint32_t)((wn*16 + (g>>1)*8 + lr) * SH7 + (g&1)*8);
    uint32_t asA[2] = { smem_u32(As[0]), smem_u32(As[1]) };
    uint32_t asB[2] = { smem_u32(Bs[0]), smem_u32(Bs[1]) };

    float acc[2][4] = {};

    auto ld = [&](int st, int kt) {
        {
            int row = tid >> 3, ch = tid & 7;
            uint32_t dst = asA[st] + (uint32_t)(row*SH7 + ch*8) * 2;
            const void* src = Ab + (size_t)row*2048 + kt*64 + ch*8;
            asm volatile("cp.async.cg.shared.global [%0], [%1], 16;" :: "r"(dst), "l"(src));
        }
#pragma unroll
        for (int j = 0; j < 2; j++) {
            int idx = j*256 + tid;
            int row = idx >> 3, ch = idx & 7;
            uint32_t dst = asB[st] + (uint32_t)(row*SH7 + ch*8) * 2;
            const void* src = g_wba + (size_t)row*2048 + kt*64 + ch*8;
            asm volatile("cp.async.cg.shared.global [%0], [%1], 16;" :: "r"(dst), "l"(src));
        }
        asm volatile("cp.async.commit_group;" ::: "memory");
    };

    ld(0, 0);
    for (int kt = 0; kt < 32; kt++) {
        if (kt + 1 < 32) {
            ld((kt + 1) & 1, kt + 1);
            asm volatile("cp.async.wait_group 1;" ::: "memory");
        } else {
            asm volatile("cp.async.wait_group 0;" ::: "memory");
        }
        __syncthreads();
        int st = kt & 1;
#pragma unroll
        for (int ks = 0; ks < 4; ks++) {
            uint32_t af[4], bf[4];
            ldmx4(af, asA[st] + (aoff + ks*16) * 2);
            ldmx4(bf, asB[st] + (boff + ks*16) * 2);
            mma_f16(acc[0], af, bf);
            mma_f16(acc[1], af, bf + 2);
        }
        __syncthreads();
    }

    int rr = lane >> 2, cc = (lane & 3) * 2;
    int row0 = bm * 32 + wm * 16 + rr;
#pragma unroll
    for (int ni = 0; ni < 2; ni++) {
        int col = wn * 16 + ni * 8 + cc;
        *(float2*)&g_ba[(size_t)row0 * 64 + col]       = make_float2(acc[ni][0], acc[ni][1]);
        *(float2*)&g_ba[(size_t)(row0 + 8) * 64 + col] = make_float2(acc[ni][2], acc[ni][3]);
    }
}

// -------- conv + silu + l2norm + head transpose + gates (float4-vectorized) --------
__global__ void conv_gate(const float* __restrict__ cw, const float* __restrict__ dtb,
                          const float* __restrict__ Alog) {
    int bs = blockIdx.x;
    int b = bs / S_, s = bs % S_;
    int tid = threadIdx.x;
    __shared__ float cs[CONV_DIM];
    __shared__ float hsum[32];
    const float* base = g_qkvz + (size_t)bs * QKVZ_N;
    const float4* cw4 = (const float4*)cw;

    for (int c4 = tid; c4 < CONV_DIM / 4; c4 += 256) {
        int c = c4 * 4;
        float4 w0 = cw4[c + 0], w1 = cw4[c + 1], w2 = cw4[c + 2], w3 = cw4[c + 3];
        float4 x3 = *(const float4*)&base[c];
        float4 r;
        r.x = x3.x * w0.w; r.y = x3.y * w1.w; r.z = x3.z * w2.w; r.w = x3.w * w3.w;
        if (s >= 1) {
            float4 x2 = *(const float4*)&base[c - (size_t)QKVZ_N];
            r.x += x2.x * w0.z; r.y += x2.y * w1.z; r.z += x2.z * w2.z; r.w += x2.w * w3.z;
        }
        if (s >= 2) {
            float4 x1 = *(const float4*)&base[c - (size_t)2*QKVZ_N];
            r.x += x1.x * w0.y; r.y += x1.y * w1.y; r.z += x1.z * w2.y; r.w += x1.w * w3.y;
        }
        if (s >= 3) {
            float4 x0 = *(const float4*)&base[c - (size_t)3*QKVZ_N];
            r.x += x0.x * w0.x; r.y += x0.y * w1.x; r.z += x0.z * w2.x; r.w += x0.w * w3.x;
        }
        r.x = r.x / (1.f + __expf(-r.x));
        r.y = r.y / (1.f + __expf(-r.y));
        r.z = r.z / (1.f + __expf(-r.z));
        r.w = r.w / (1.f + __expf(-r.w));
        *(float4*)&cs[c] = r;
    }
    __syncthreads();
    int warp = tid >> 5, lane = tid & 31;
    for (int h = warp; h < 32; h += 8) {
        float ss = 0.f;
        for (int d = lane; d < 128; d += 32) { float v = cs[h*128 + d]; ss += v * v; }
#pragma unroll
        for (int o = 16; o; o >>= 1) ss += __shfl_xor_sync(~0u, ss, o);
        if (!lane) hsum[h] = rsqrtf(ss + 1e-6f);
    }
    __syncthreads();
    for (int c4 = tid; c4 < KEY_DIM / 4; c4 += 256) {
        int c = c4 * 4;
        int h = c >> 7, d = c & 127;
        float sc = hsum[h] * QSCALE;
        float4 v = *(float4*)&cs[c];
        v.x *= sc; v.y *= sc; v.z *= sc; v.w *= sc;
        *(float4*)&g_q[(((size_t)b*HKq + h)*S_ + s)*DKd + d] = v;
    }
    for (int c4 = tid; c4 < KEY_DIM / 4; c4 += 256) {
        int c = c4 * 4;
        int h = c >> 7, d = c & 127;
        float sc = hsum[16 + h];
        float4 v = *(float4*)&cs[KEY_DIM + c];
        v.x *= sc; v.y *= sc; v.z *= sc; v.w *= sc;
        *(float4*)&g_k[(((size_t)b*HKq + h)*S_ + s)*DKd + d] = v;
    }
    for (int c4 = tid; c4 < VALUE_DIM / 4; c4 += 256) {
        int c = c4 * 4;
        int h = c >> 7, d = c & 127;
        float4 v = *(float4*)&cs[2*KEY_DIM + c];
        *(float4*)&g_v[(((size_t)b*HVv + h)*S_ + s)*DVd + d] = v;
    }
    if (tid < 64) {
        float bb = g_ba[(size_t)bs * 64 + tid];
        if (tid < 32) {
            g_beta[((size_t)b*HVv + tid)*S_ + s] = 1.f / (1.f + expf(-bb));
        } else {
            int h = tid - 32;
            float a = bb + dtb[h];
            float sp = (a > 20.f) ? a : log1pf(expf(a));
            g_g[((size_t)b*HVv + h)*S_ + s] = -expf(Alog[h]) * sp;
        }
    }
}

// ======== chunk_prep: grid (b*hq*n)=1024; HMMA dots; dual-head T-solve ========
__global__ void __launch_bounds__(256, 1) chunk_prep() {
    extern __shared__ char smraw[];
    float* k_s   = (float*)smraw;
    float* vb_s  = k_s + 64*SW;
    float* dotsA = vb_s + 64*SW;
    float* dotsQ = dotsA + 4096;
    float* A2    = dotsQ + 4096;
    float* T2    = A2 + 8192;
    __half* k16  = (__half*)(T2 + 8320);
    __half* q16  = k16 + 64*SH6;
    __shared__ float gc2[2][64], beta2[2][64], kbe2[2][64];

    int blk = blockIdx.x;
    int n = blk & 31, hq = (blk >> 5) & 15, b = blk >> 9;
    int tid = threadIdx.x, lane = tid & 31, wid = tid >> 5;

    size_t qk_off = (((size_t)b*HKq + hq)*S_ + (size_t)n*CHUNK) * DKd;

    for (int idx = tid; idx < 2048; idx += 256) {
        int r = idx >> 5, d = (idx & 31) * 4;
        float4 qv = *(const float4*)&g_q[qk_off + (size_t)r*128 + d];
        float4 kv = *(const float4*)&g_k[qk_off + (size_t)r*128 + d];
        *(float4*)&k_s[r*SW + d] = kv;
        *(__half2*)&q16[r*SH6 + d]     = __floats2half2_rn(qv.x, qv.y);
        *(__half2*)&q16[r*SH6 + d + 2] = __floats2half2_rn(qv.z, qv.w);
        *(__half2*)&k16[r*SH6 + d]     = __floats2half2_rn(kv.x, kv.y);
        *(__half2*)&k16[r*SH6 + d + 2] = __floats2half2_rn(kv.z, kv.w);
    }
    if (tid < 128) {
        int hh = tid >> 6, i = tid & 63;
        size_t gb = ((size_t)b*HVv + hq*2 + hh)*S_ + (size_t)n*CHUNK;
        gc2[hh][i] = g_g[gb + i];
        beta2[hh][i] = g_beta[gb + i];
    }
    __syncthreads();
    if (tid < 2) {
        float* gcp = gc2[tid];
        for (int i = 1; i < 64; i++) gcp[i] += gcp[i - 1];
    }
    __syncthreads();
    if (tid < 128) {
        int hh = tid >> 6, i = tid & 63;
        size_t gb = ((size_t)b*HVv + hq*2 + hh)*S_ + (size_t)n*CHUNK;
        g_gc[gb + i] = gc2[hh][i];
        kbe2[hh][i] = beta2[hh][i] * expf(gc2[hh][i]);
    }

    {
        int mW = (wid >> 1) * 16, nW = (wid & 1) * 32;
        int g = lane >> 3, lr = lane & 7;
        uint32_t aK = smem_u32(k16) + 2u*(uint32_t)((mW + (g&1)*8 + lr)*SH6 + (g>>1)*8);
        uint32_t aQ = smem_u32(q16) + 2u*(uint32_t)((mW + (g&1)*8 + lr)*SH6 + (g>>1)*8);
        uint32_t bK = smem_u32(k16) + 2u*(uint32_t)((nW + (g>>1)*8 + lr)*SH6 + (g&1)*8);
        float accK[4][4], accQ[4][4];
#pragma unroll
        for (int i = 0; i < 4; i++)
#pragma unroll
            for (int r = 0; r < 4; r++) { accK[i][r] = 0.f; accQ[i][r] = 0.f; }
#pragma unroll
        for (int kt = 0; kt < 8; kt++) {
            uint32_t afk[4], afq[4], b0[4], b1[4];
            ldmx4(afk, aK + 2u*(kt*16));
            ldmx4(afq, aQ + 2u*(kt*16));
            ldmx4(b0, bK + 2u*(kt*16));
            ldmx4(b1, bK + 2u*(16*SH6 + kt*16));
            mma_f16(accK[0], afk, b0); mma_f16(accK[1], afk, b0 + 2);
            mma_f16(accK[2], afk, b1); mma_f16(accK[3], afk, b1 + 2);
            mma_f16(accQ[0], afq, b0); mma_f16(accQ[1], afq, b0 + 2);
            mma_f16(accQ[2], afq, b1); mma_f16(accQ[3], afq, b1 + 2);
        }
        int rr = lane >> 2, cc = (lane & 3) * 2;
#pragma unroll
        for (int ni = 0; ni < 4; ni++) {
            int j = nW + ni*8 + cc;
            int c0r = mW + rr;
            *(float2*)&dotsA[c0r*64 + j]     = make_float2(accK[ni][0], accK[ni][1]);
            *(float2*)&dotsA[(c0r+8)*64 + j] = make_float2(accK[ni][2], accK[ni][3]);
            *(float2*)&dotsQ[c0r*64 + j]     = make_float2(accQ[ni][0], accQ[ni][1]);
            *(float2*)&dotsQ[(c0r+8)*64 + j] = make_float2(accQ[ni][2], accQ[ni][3]);
        }
    }
    __syncthreads();

    for (int idx = tid; idx < 8192; idx += 256) {
        int hh = idx >> 12, i = idx & 4095;
        int c = i >> 6, j = i & 63;
        float e = __expf(gc2[hh][c] - gc2[hh][j]);
        A2[hh*4096 + i] = (j < c) ? dotsA[i] * beta2[hh][c] * e : 0.f;
        size_t at_off = (((size_t)b*HVv + hq*2 + hh)*S_ + (size_t)n*CHUNK) * CHUNK;
        g_attn[at_off + i] = (j <= c) ? dotsQ[i] * e : 0.f;
    }
    __syncthreads();

    if (tid < 128) {
        int hh = tid >> 6, col = tid & 63;
        float* A_s = A2 + hh*4096;
        float* T_s = T2 + hh*4160;
        for (int c = 0; c < 64; c++) {
            float ssum = (c == col) ? 1.f : 0.f;
            for (int j = col; j < c; j++) ssum -= A_s[c*64 + j] * T_s[j*65 + col];
            T_s[c*65 + col] = (c >= col) ? ssum : 0.f;
        }
    }
    __syncthreads();

#pragma unroll 1
    for (int h2 = 0; h2 < 2; h2++) {
        int h = hq * 2 + h2;
        size_t v_off  = (((size_t)b*HVv + h)*S_ + (size_t)n*CHUNK) * DVd;
        size_t gb_off = ((size_t)b*HVv + h)*S_ + (size_t)n*CHUNK;
        float* T_s = T2 + h2*4160;

        for (int idx = tid; idx < 2048; idx += 256) {
            int r = idx >> 5, d = (idx & 31) * 4;
            float4 vv = *(const float4*)&g_v[v_off + (size_t)r*128 + d];
            float be = beta2[h2][r];
            vv.x *= be; vv.y *= be; vv.z *= be; vv.w *= be;
            *(float4*)&vb_s[r*SW + d] = vv;
        }
        __syncthreads();

        {
            int ct8 = tid >> 5, lane2 = tid & 31;
            int c0 = ct8 * 8, d0 = lane2 * 4;
            float av[8][4] = {}, ak[8][4] = {};
            int jmax = c0 + 8;
            for (int j = 0; j < jmax; j++) {
                float4 vv = *(float4*)&vb_s[j*SW + d0];
                float4 kk = *(float4*)&k_s [j*SW + d0];
                float kb = kbe2[h2][j];
                kk.x *= kb; kk.y *= kb; kk.z *= kb; kk.w *= kb;
#pragma unroll
                for (int ci = 0; ci < 8; ci++) {
                    float t = T_s[(c0+ci)*65 + j];
                    av[ci][0] += t*vv.x; av[ci][1] += t*vv.y; av[ci][2] += t*vv.z; av[ci][3] += t*vv.w;
                    ak[ci][0] += t*kk.x; ak[ci][1] += t*kk.y; ak[ci][2] += t*kk.z; ak[ci][3] += t*kk.w;
                }
            }
            size_t kcd_off = gb_off * DKd;
#pragma unroll
            for (int ci = 0; ci < 8; ci++) {
                *(float4*)&g_vadj[v_off   + (size_t)(c0+ci)*128 + d0] =
                    make_float4(av[ci][0], av[ci][1], av[ci][2], av[ci][3]);
                *(float4*)&g_kcd [kcd_off + (size_t)(c0+ci)*128 + d0] =
                    make_float4(ak[ci][0], ak[ci][1], ak[ci][2], ak[ci][3]);
            }
        }
        __syncthreads();
    }
}

// ======== HMMA scan: state_T fp32 [dv][dk]; per-chunk fp16 operand tiles ========
__global__ void __launch_bounds__(512, 1) scan_kernel() {
    extern __shared__ char smraw[];
    float*  stT  = (float*)smraw;
    __half* st16 = (__half*)(stT + 64*STF);
    __half* kcd16= st16 + 64*SH6;
    __half* q16  = kcd16 + 64*SH6;
    __half* kT16 = q16 + 64*SH6;
    __half* at16 = kT16 + 128*SH7;
    __half* vnT16= at16 + 64*SH7;
    __half* vkT16= vnT16 + 64*SH7;
    __shared__ float eg_s[64], ek_s[64];

    int bh = blockIdx.x, dvt = blockIdx.y;
    int b = bh >> 5, h = bh & 31, hq = h >> 1;
    int tid = threadIdx.x, lane = tid & 31, wid = tid >> 5;

    int mW = (wid >> 2) * 16;
    int nW = (wid & 3) * 16;
    int g = lane >> 3, lr = lane & 7;
    int rr = lane >> 2, cc = (lane & 3) * 2;

    for (int i = tid; i < 64*STF; i += 512) stT[i] = 0.f;
    for (int i = tid; i < 64*SH6; i += 512) st16[i] = __float2half(0.f);

    uint32_t aKCD = smem_u32(kcd16) + 2u*((mW + (g&1)*8 + lr)*SH6 + (g>>1)*8);
    uint32_t aQ   = smem_u32(q16)   + 2u*((mW + (g&1)*8 + lr)*SH6 + (g>>1)*8);
    uint32_t aAT  = smem_u32(at16)  + 2u*((mW + (g&1)*8 + lr)*SH7 + (g>>1)*8);
    uint32_t bST  = smem_u32(st16)  + 2u*((nW + (g>>1)*8 + lr)*SH6 + (g&1)*8);
    uint32_t bVN  = smem_u32(vnT16) + 2u*((nW + (g>>1)*8 + lr)*SH7 + (g&1)*8);

    for (int n = 0; n < NCH; n++) {
        size_t qk_off = (((size_t)b*HKq + hq)*S_ + (size_t)n*CHUNK) * DKd;
        size_t kv_off = (((size_t)b*HVv + h )*S_ + (size_t)n*CHUNK) * DKd;
        size_t gb_off = ((size_t)b*HVv + h)*S_ + (size_t)n*CHUNK;

        __syncthreads();
        for (int idx = tid; idx < 2048; idx += 512) {
            int r = idx >> 5, d = (idx & 31) * 4;
            float4 kc = *(const float4*)&g_kcd[kv_off + (size_t)r*128 + d];
            float4 qv = *(const float4*)&g_q  [qk_off + (size_t)r*128 + d];
            float4 kv = *(const float4*)&g_k  [qk_off + (size_t)r*128 + d];
            *(__half2*)&kcd16[r*SH6 + d]     = __floats2half2_rn(-kc.x, -kc.y);
            *(__half2*)&kcd16[r*SH6 + d + 2] = __floats2half2_rn(-kc.z, -kc.w);
            *(__half2*)&q16[r*SH6 + d]       = __floats2half2_rn(qv.x, qv.y);
            *(__half2*)&q16[r*SH6 + d + 2]   = __floats2half2_rn(qv.z, qv.w);
            kT16[(d+0)*SH7 + r] = __float2half_rn(kv.x);
            kT16[(d+1)*SH7 + r] = __float2half_rn(kv.y);
            kT16[(d+2)*SH7 + r] = __float2half_rn(kv.z);
            kT16[(d+3)*SH7 + r] = __float2half_rn(kv.w);
        }
        for (int idx = tid; idx < 1024; idx += 512) {
            int c = idx >> 4, j = (idx & 15) * 4;
            float4 av = *(const float4*)&g_attn[gb_off*CHUNK + (size_t)c*64 + j];
            *(__half2*)&at16[c*SH7 + j]     = __floats2half2_rn(av.x, av.y);
            *(__half2*)&at16[c*SH7 + j + 2] = __floats2half2_rn(av.z, av.w);
        }
        if (tid < 64) {
            float gv = g_gc[gb_off + tid];
            float gl = g_gc[gb_off + 63];
            eg_s[tid] = expf(gv);
            ek_s[tid] = expf(gl - gv);
        }
        __syncthreads();

        // ---- M1 ----
        float c0[4], c1[4];
        {
            size_t vb = kv_off + (size_t)(mW + rr)*128 + dvt*64 + nW + cc;
            float2 t;
            t = *(const float2*)&g_vadj[vb];              c0[0]=t.x; c0[1]=t.y;
            t = *(const float2*)&g_vadj[vb + 8*128];      c0[2]=t.x; c0[3]=t.y;
            t = *(const float2*)&g_vadj[vb + 8];          c1[0]=t.x; c1[1]=t.y;
            t = *(const float2*)&g_vadj[vb + 8*128 + 8];  c1[2]=t.x; c1[3]=t.y;
        }
#pragma unroll
        for (int kt = 0; kt < 8; kt++) {
            uint32_t af[4], bf[4];
            ldmx4(af, aKCD + 2u*(kt*16));
            ldmx4(bf, bST  + 2u*(kt*16));
            mma_f16(c0, af, bf);
            mma_f16(c1, af, bf + 2);
        }
        {
            int cr0 = mW + rr, cr1 = mW + rr + 8;
            int d0 = nW + cc, d1 = nW + 8 + cc;
            float e0 = ek_s[cr0], e1 = ek_s[cr1];
            vnT16[(d0  )*SH7 + cr0] = __float2half_rn(c0[0]);
            vnT16[(d0+1)*SH7 + cr0] = __float2half_rn(c0[1]);
            vnT16[(d0  )*SH7 + cr1] = __float2half_rn(c0[2]);
            vnT16[(d0+1)*SH7 + cr1] = __float2half_rn(c0[3]);
            vnT16[(d1  )*SH7 + cr0] = __float2half_rn(c1[0]);
            vnT16[(d1+1)*SH7 + cr0] = __float2half_rn(c1[1]);
            vnT16[(d1  )*SH7 + cr1] = __float2half_rn(c1[2]);
            vnT16[(d1+1)*SH7 + cr1] = __float2half_rn(c1[3]);
            vkT16[(d0  )*SH7 + cr0] = __float2half_rn(c0[0]*e0);
            vkT16[(d0+1)*SH7 + cr0] = __float2half_rn(c0[1]*e0);
            vkT16[(d0  )*SH7 + cr1] = __float2half_rn(c0[2]*e1);
            vkT16[(d0+1)*SH7 + cr1] = __float2half_rn(c0[3]*e1);
            vkT16[(d1  )*SH7 + cr0] = __float2half_rn(c1[0]*e0);
            vkT16[(d1+1)*SH7 + cr0] = __float2half_rn(c1[1]*e0);
            vkT16[(d1  )*SH7 + cr1] = __float2half_rn(c1[2]*e1);
            vkT16[(d1+1)*SH7 + cr1] = __float2half_rn(c1[3]*e1);
        }
        __syncthreads();

        // ---- M2 ----
        float o0[4] = {0,0,0,0}, o1[4] = {0,0,0,0};
#pragma unroll
        for (int kt = 0; kt < 8; kt++) {
            uint32_t af[4], bf[4];
            ldmx4(af, aQ  + 2u*(kt*16));
            ldmx4(bf, bST + 2u*(kt*16));
            mma_f16(o0, af, bf);
            mma_f16(o1, af, bf + 2);
        }
        {
            float e0 = eg_s[mW + rr], e1 = eg_s[mW + rr + 8];
            o0[0]*=e0; o0[1]*=e0; o0[2]*=e1; o0[3]*=e1;
            o1[0]*=e0; o1[1]*=e0; o1[2]*=e1; o1[3]*=e1;
        }
#pragma unroll
        for (int kt = 0; kt < 4; kt++) {
            uint32_t af[4], bf[4];
            ldmx4(af, aAT + 2u*(kt*16));
            ldmx4(bf, bVN + 2u*(kt*16));
            mma_f16(o0, af, bf);
            mma_f16(o1, af, bf + 2);
        }
        {
            size_t ob = ((size_t)b*S_ + (size_t)n*CHUNK + mW + rr)*VALUE_DIM
                      + (size_t)h*DVd + dvt*64 + nW + cc;
            *(float2*)&g_o[ob]                       = make_float2(o0[0], o0[1]);
            *(float2*)&g_o[ob + 8*(size_t)VALUE_DIM] = make_float2(o0[2], o0[3]);
            *(float2*)&g_o[ob + 8]                   = make_float2(o1[0], o1[1]);
            *(float2*)&g_o[ob + 8*(size_t)VALUE_DIM + 8] = make_float2(o1[2], o1[3]);
        }
        __syncthreads();

        // ---- M3 ----
        float egl = eg_s[63];
#pragma unroll
        for (int i = 0; i < 2; i++) {
            int t = wid * 2 + i;
            int dv0 = (t >> 3) * 16, dk0 = (t & 7) * 16;
            float s0[4], s1[4];
            float* sp  = &stT[(dv0 + rr)*STF + dk0 + cc];
            float* sp8 = &stT[(dv0 + rr + 8)*STF + dk0 + cc];
            s0[0] = sp[0]*egl;  s0[1] = sp[1]*egl;
            s1[0] = sp[8]*egl;  s1[1] = sp[9]*egl;
            s0[2] = sp8[0]*egl; s0[3] = sp8[1]*egl;
            s1[2] = sp8[8]*egl; s1[3] = sp8[9]*egl;
            uint32_t aV = smem_u32(vkT16) + 2u*((dv0 + (g&1)*8 + lr)*SH7 + (g>>1)*8);
            uint32_t bK = smem_u32(kT16)  + 2u*((dk0 + (g>>1)*8 + lr)*SH7 + (g&1)*8);
#pragma unroll
            for (int kt = 0; kt < 4; kt++) {
                uint32_t af[4], bf[4];
                ldmx4(af, aV + 2u*(kt*16));
                ldmx4(bf, bK + 2u*(kt*16));
                mma_f16(s0, af, bf);
                mma_f16(s1, af, bf + 2);
            }
            sp[0]=s0[0];  sp[1]=s0[1];  sp[8]=s1[0];  sp[9]=s1[1];
            sp8[0]=s0[2]; sp8[1]=s0[3]; sp8[8]=s1[2]; sp8[9]=s1[3];
            *(__half2*)&st16[(dv0+rr)*SH6 + dk0 + cc]       = __floats2half2_rn(s0[0], s0[1]);
            *(__half2*)&st16[(dv0+rr)*SH6 + dk0 + 8 + cc]   = __floats2half2_rn(s1[0], s1[1]);
            *(__half2*)&st16[(dv0+rr+8)*SH6 + dk0 + cc]     = __floats2half2_rn(s0[2], s0[3]);
            *(__half2*)&st16[(dv0+rr+8)*SH6 + dk0 + 8 + cc] = __floats2half2_rn(s1[2], s1[3]);
        }
    }
}

// -------- gated RMSNorm -> fp16 directly into GEMM2 A buffer --------
__global__ void gated_norm(const float* __restrict__ nw) {
    int bs = blockIdx.x;
    int warp = threadIdx.x >> 5, lane = threadIdx.x & 31;
    for (int h = warp; h < HVv; h += 8) {
        size_t off = (size_t)bs * VALUE_DIM + (size_t)h * DVd;
        float4 v = ((float4*)(g_o + off))[lane];
        float ss = v.x*v.x + v.y*v.y + v.z*v.z + v.w*v.w;
#pragma unroll
        for (int o = 16; o; o >>= 1) ss += __shfl_xor_sync(~0u, ss, o);
        float r = rsqrtf(ss / 128.f + 1e-6f);
        size_t zoff = (size_t)bs * QKVZ_N + 2*KEY_DIM + VALUE_DIM + (size_t)h * DVd;
        float4 z = ((const float4*)(g_qkvz + zoff))[lane];
        float4 w = ((const float4*)nw)[lane];
        float r0 = v.x * r * w.x * (z.x / (1.f + expf(-z.x)));
        float r1 = v.y * r * w.y * (z.y / (1.f + expf(-z.y)));
        float r2 = v.z * r * w.z * (z.z / (1.f + expf(-z.z)));
        float r3 = v.w * r * w.w * (z.w / (1.f + expf(-z.w)));
        __half2 h0 = __floats2half2_rn(r0, r1);
        __half2 h1 = __floats2half2_rn(r2, r3);
        uint2 hv; hv.x = *(uint32_t*)&h0; hv.y = *(uint32_t*)&h1;
        ((uint2*)(g_r + off))[lane] = hv;
    }
}

// ---------------- launcher (single stream) ----------------
extern "C" void kernel_launch(void* const* d_in, const int* in_sizes, int n_in,
                              void* d_out, int out_size) {
    const float* hidden = (const float*)d_in[0];
    const float* Wqkvz  = (const float*)d_in[1];
    const float* Wba    = (const float*)d_in[2];
    const float* convw  = (const float*)d_in[3];
    const float* dtb    = (const float*)d_in[4];
    const float* Alog   = (const float*)d_in[5];
    const float* nw     = (const float*)d_in[6];
    const float* Wout   = (const float*)d_in[7];
    float* out = (float*)d_out;

    float *qkvz_p;
    __half *p_p, *r_p, *wba_p;
    cudaGetSymbolAddress((void**)&qkvz_p, g_qkvz);
    cudaGetSymbolAddress((void**)&p_p, g_p);
    cudaGetSymbolAddress((void**)&r_p, g_r);
    cudaGetSymbolAddress((void**)&wba_p, g_wba);

    const int SMEM3 = (2*64*SW + 2*4096 + 2*4096 + 2*64*65) * 4 + 2*64*SH6 * 2;
    const int SMEM4 = 64*STF*4 + (3*64*SH6 + 128*SH7 + 3*64*SH7) * 2;
    const int SMEM_MM = NSTG * STG1 * 2;
    cudaFuncSetAttribute(chunk_prep, cudaFuncAttributeMaxDynamicSharedMemorySize, SMEM3);
    cudaFuncSetAttribute(scan_kernel, cudaFuncAttributeMaxDynamicSharedMemorySize, SMEM4);
    cudaFuncSetAttribute(mmgemm, cudaFuncAttributeMaxDynamicSharedMemorySize, SMEM_MM);

    // --- operand conversions ---
    cvt_h<<<(BSz*(size_t)HID)/1024, 256>>>(hidden, p_p);
    cvt_T<<<dim3(QKVZ_N/32, HID/32), dim3(32,8)>>>(Wqkvz, r_p, HID, QKVZ_N);
    cvt_T<<<dim3(2, HID/32), dim3(32,8)>>>(Wba, wba_p, HID, 64);

    // --- GEMM1: qkvz = hidden @ W_qkvz ---
    mmgemm<<<dim3(BSz/128, QKVZ_N/128), 256, SMEM_MM>>>(p_p, r_p, qkvz_p, BSz, QKVZ_N, HID);

    // --- BA projection (HMMA) ---
    gemm_ba_h<<<BSz/32, 256>>>(p_p);

    // --- conv + gates, chunk prep, scan, norm ---
    conv_gate<<<BSz, 256>>>(convw, dtb, Alog);
    chunk_prep<<<B_*HKq*NCH, 256, SMEM3>>>();
    scan_kernel<<<dim3(B_*HVv, 2), 512, SMEM4>>>();
    gated_norm<<<BSz, 256>>>(nw);

    // --- GEMM2: out = o @ W_out ---
    cvt_T<<<dim3(HID/32, VALUE_DIM/32), dim3(32,8)>>>(Wout, p_p, VALUE_DIM, HID);
    mmgemm<<<dim3(BSz/128, HID/128), 256, SMEM_MM>>>(r_p, p_p, out, BSz, HID, VALUE_DIM);
}

// round 16
// speedup vs baseline: 1.0205x; 1.0205x over previous
#include <cuda_runtime.h>
#include <cuda_bf16.h>
#include <cuda_fp16.h>
#include <math.h>
#include <stdint.h>

// ---------------- problem constants ----------------
#define B_   2
#define S_   2048
#define HID  2048
#define HKq  16
#define HVv  32
#define DKd  128
#define DVd  128
#define KC   4
#define CHUNK 64
#define NCH  (S_/CHUNK)          // 32
#define KEY_DIM 2048
#define VALUE_DIM 4096
#define CONV_DIM 8192
#define QKVZ_N 12288
#define BSz  (B_*S_)             // 4096
#define QSCALE 0.08838834764831845f   // DK^-0.5
#define SW 132
#define STF 132
#define SH6 136
#define SH7 72

// ---------------- scratch (static device memory; no allocations) ------------
__device__ float g_qkvz[(size_t)BSz*QKVZ_N];
__device__ float g_ba[(size_t)BSz*64];
__device__ float g_q[(size_t)B_*HKq*S_*DKd];
__device__ float g_k[(size_t)B_*HKq*S_*DKd];
__device__ float g_v[(size_t)B_*HVv*S_*DVd];
__device__ float g_g[(size_t)B_*HVv*S_];
__device__ float g_beta[(size_t)B_*HVv*S_];
__device__ float g_gc[(size_t)B_*HVv*S_];
__device__ float g_vadj[(size_t)B_*HVv*S_*DVd];
__device__ float g_kcd[(size_t)B_*HVv*S_*DKd];
__device__ float g_attn[(size_t)B_*HVv*S_*CHUNK];
__device__ float g_o[(size_t)BSz*VALUE_DIM];

__device__ __half g_p [(size_t)8388608];    // A1 (hidden) / B2t (Wout^T)
__device__ __half g_r [(size_t)25165824];   // B1t (Wqkvz^T) ; later A2
__device__ __half g_wba[(size_t)64*2048];   // W_ba^T fp16

__device__ __forceinline__ uint32_t smem_u32(const void* p) {
    uint32_t a;
    asm("{ .reg .u64 t; cvta.to.shared.u64 t, %1; cvt.u32.u64 %0, t; }" : "=r"(a) : "l"(p));
    return a;
}

// ---------------- fp32 -> fp16 (elementwise, float4) ----------------
__global__ void cvt_h(const float* __restrict__ X, __half* __restrict__ H) {
    size_t i = ((size_t)blockIdx.x * 256 + threadIdx.x) * 4;
    float4 v = *(const float4*)&X[i];
    __half2 h0 = __floats2half2_rn(v.x, v.y);
    __half2 h1 = __floats2half2_rn(v.z, v.w);
    uint2 hv;
    hv.x = *(uint32_t*)&h0; hv.y = *(uint32_t*)&h1;
    *(uint2*)&H[i] = hv;
}

// ---------------- fp32 [K,N] -> fp16 [N,K] transpose ----------------
__global__ void cvt_T(const float* __restrict__ W, __half* __restrict__ Ht, int K, int N) {
    __shared__ float tile[32][33];
    int n0 = blockIdx.x * 32, k0 = blockIdx.y * 32;
    int tx = threadIdx.x, ty = threadIdx.y;
#pragma unroll
    for (int j = 0; j < 32; j += 8)
        tile[ty + j][tx] = W[(size_t)(k0 + ty + j) * N + n0 + tx];
    __syncthreads();
#pragma unroll
    for (int j = 0; j < 32; j += 8)
        Ht[(size_t)(n0 + ty + j) * K + k0 + tx] = __float2half_rn(tile[tx][ty + j]);
}

// ============ fp16 HMMA GEMM: C[M,N] = A[M,K] @ Bt[N,K]^T (fp32 accum) ============
// 4 stages, prefetch distance 2, ONE barrier per ktile.
#define PSH 40
#define TEN2 (128*PSH)
#define STG1 (2*TEN2)
#define NSTG 4

__device__ __forceinline__ void mma_f16(float* c, const uint32_t* a, const uint32_t* b) {
    asm volatile("mma.sync.aligned.m16n8k16.row.col.f32.f16.f16.f32 "
                 "{%0,%1,%2,%3}, {%4,%5,%6,%7}, {%8,%9}, {%0,%1,%2,%3};"
                 : "+f"(c[0]), "+f"(c[1]), "+f"(c[2]), "+f"(c[3])
                 : "r"(a[0]), "r"(a[1]), "r"(a[2]), "r"(a[3]), "r"(b[0]), "r"(b[1]));
}
__device__ __forceinline__ void ldmx4(uint32_t* r, uint32_t addr) {
    asm volatile("ldmatrix.sync.aligned.m8n8.x4.shared.b16 {%0,%1,%2,%3}, [%4];"
                 : "=r"(r[0]), "=r"(r[1]), "=r"(r[2]), "=r"(r[3]) : "r"(addr));
}

__device__ __forceinline__ void stage_load(uint32_t sbase_b, int stage,
    const __half* a0, const __half* b0, int K, int kt, int tid)
{
    const __half* gp[2] = {a0, b0};
    uint32_t st_b = sbase_b + (uint32_t)stage * (STG1 * 2);
#pragma unroll
    for (int t = 0; t < 2; t++) {
        uint32_t tb = st_b + (uint32_t)t * (TEN2 * 2);
#pragma unroll
        for (int j = 0; j < 2; j++) {
            int idx = j * 256 + tid;
            int row = idx >> 2, c16 = idx & 3;
            uint32_t sa = tb + (uint32_t)(row * (PSH*2) + c16 * 16);
            const void* ga = gp[t] + (size_t)row * K + (size_t)kt * 32 + c16 * 8;
            asm volatile("cp.async.cg.shared.global [%0], [%1], 16;" :: "r"(sa), "l"(ga));
        }
    }
    asm volatile("cp.async.commit_group;" ::: "memory");
}

__global__ void __launch_bounds__(256, 2) mmgemm(
    const __half* __restrict__ Ah, const __half* __restrict__ Bh,
    float* __restrict__ C, int M, int N, int K)
{
    extern __shared__ __half smem[];
    uint32_t sbase = smem_u32(smem);
    int tid = threadIdx.x, lane = tid & 31, wid = tid >> 5;
    int warpM = wid >> 2, warpN = wid & 3;
    int bm = blockIdx.x, bn = blockIdx.y;
    const int T = K >> 5;

    const __half* a0 = Ah + (size_t)bm * 128 * K;
    const __half* b0 = Bh + (size_t)bn * 128 * K;

    int g = lane >> 3, lr = lane & 7;
    uint32_t aoff = (uint32_t)((warpM*64 + (g&1)*8 + lr) * PSH + (g>>1)*8);
    uint32_t boff = (uint32_t)((warpN*32 + (g>>1)*8 + lr) * PSH + (g&1)*8);

    float acc[4][4][4];
#pragma unroll
    for (int i = 0; i < 4; i++)
#pragma unroll
        for (int j = 0; j < 4; j++)
#pragma unroll
            for (int r = 0; r < 4; r++) acc[i][j][r] = 0.f;

    stage_load(sbase, 0, a0, b0, K, 0, tid);
    stage_load(sbase, 1, a0, b0, K, 1, tid);

    for (int kt = 0; kt < T; kt++) {
        if (kt + 1 < T) asm volatile("cp.async.wait_group 1;" ::: "memory");
        else            asm volatile("cp.async.wait_group 0;" ::: "memory");
        __syncthreads();
        // prefetch kt+2 into stage (kt+2)%4 — disjoint from stage kt%4 being
        // read this iteration and from stage (kt+1)%4 in flight; last read of
        // (kt+2)%4 finished before sync(kt) (<=1-iteration warp skew).
        if (kt + 2 < T) stage_load(sbase, (kt + 2) % NSTG, a0, b0, K, kt + 2, tid);

        uint32_t st = sbase + (uint32_t)(kt % NSTG) * (STG1 * 2);
        uint32_t sA = st, sB = st + TEN2*2;
#pragma unroll
        for (int ks = 0; ks < 2; ks++) {
            int kk = ks * 16;
            uint32_t ah[4][4], bh[4][2];
#pragma unroll
            for (int mi = 0; mi < 4; mi++)
                ldmx4(ah[mi], sA + (aoff + mi*16*PSH + kk) * 2);
#pragma unroll
            for (int p = 0; p < 2; p++) {
                uint32_t rh[4];
                ldmx4(rh, sB + (boff + p*16*PSH + kk) * 2);
                bh[2*p][0] = rh[0]; bh[2*p][1] = rh[1];
                bh[2*p+1][0] = rh[2]; bh[2*p+1][1] = rh[3];
            }
#pragma unroll
            for (int mi = 0; mi < 4; mi++)
#pragma unroll
                for (int ni = 0; ni < 4; ni++)
                    mma_f16(acc[mi][ni], ah[mi], bh[ni]);
        }
    }

    int rr = lane >> 2, cc = (lane & 3) * 2;
#pragma unroll
    for (int mi = 0; mi < 4; mi++) {
        int row0 = bm * 128 + warpM * 64 + mi * 16 + rr;
#pragma unroll
        for (int ni = 0; ni < 4; ni++) {
            int col = bn * 128 + warpN * 32 + ni * 8 + cc;
            float2 v0 = make_float2(acc[mi][ni][0], acc[mi][ni][1]);
            float2 v1 = make_float2(acc[mi][ni][2], acc[mi][ni][3]);
            *(float2*)&C[(size_t)row0 * N + col]       = v0;
            *(float2*)&C[(size_t)(row0 + 8) * N + col] = v1;
        }
    }
}

// ------------- BA projection, HMMA: g_ba[BSz,64] = hidden_fp16 @ Wba^T -------------
__global__ void __launch_bounds__(256) gemm_ba_h(const __half* __restrict__ A) {
    __shared__ __half As[2][32*SH7];
    __shared__ __half Bs[2][64*SH7];
    int tid = threadIdx.x, lane = tid & 31, wid = tid >> 5;
    int bm = blockIdx.x;
    int wm = wid >> 2, wn = wid & 3;
    int g = lane >> 3, lr = lane & 7;
    const __half* Ab = A + (size_t)bm * 32 * 2048;

    uint32_t aoff = (uint32_t)((wm*16 + (g&1)*8 + lr) * SH7 + (g>>1)*8);
    uint32_t boff = (uint32_t)((wn*16 + (g>>1)*8 + lr) * SH7 + (g&1)*8);
    uint32_t asA[2] = { smem_u32(As[0]), smem_u32(As[1]) };
    uint32_t asB[2] = { smem_u32(Bs[0]), smem_u32(Bs[1]) };

    float acc[2][4] = {};

    auto ld = [&](int st, int kt) {
        {
            int row = tid >> 3, ch = tid & 7;
            uint32_t dst = asA[st] + (uint32_t)(row*SH7 + ch*8) * 2;
            const void* src = Ab + (size_t)row*2048 + kt*64 + ch*8;
            asm volatile("cp.async.cg.shared.global [%0], [%1], 16;" :: "r"(dst), "l"(src));
        }
#pragma unroll
        for (int j = 0; j < 2; j++) {
            int idx = j*256 + tid;
            int row = idx >> 3, ch = idx & 7;
            uint32_t dst = asB[st] + (uint32_t)(row*SH7 + ch*8) * 2;
            const void* src = g_wba + (size_t)row*2048 + kt*64 + ch*8;
            asm volatile("cp.async.cg.shared.global [%0], [%1], 16;" :: "r"(dst), "l"(src));
        }
        asm volatile("cp.async.commit_group;" ::: "memory");
    };

    ld(0, 0);
    for (int kt = 0; kt < 32; kt++) {
        if (kt + 1 < 32) {
            ld((kt + 1) & 1, kt + 1);
            asm volatile("cp.async.wait_group 1;" ::: "memory");
        } else {
            asm volatile("cp.async.wait_group 0;" ::: "memory");
        }
        __syncthreads();
        int st = kt & 1;
#pragma unroll
        for (int ks = 0; ks < 4; ks++) {
            uint32_t af[4], bf[4];
            ldmx4(af, asA[st] + (aoff + ks*16) * 2);
            ldmx4(bf, asB[st] + (boff + ks*16) * 2);
            mma_f16(acc[0], af, bf);
            mma_f16(acc[1], af, bf + 2);
        }
        __syncthreads();
    }

    int rr = lane >> 2, cc = (lane & 3) * 2;
    int row0 = bm * 32 + wm * 16 + rr;
#pragma unroll
    for (int ni = 0; ni < 2; ni++) {
        int col = wn * 16 + ni * 8 + cc;
        *(float2*)&g_ba[(size_t)row0 * 64 + col]       = make_float2(acc[ni][0], acc[ni][1]);
        *(float2*)&g_ba[(size_t)(row0 + 8) * 64 + col] = make_float2(acc[ni][2], acc[ni][3]);
    }
}

// -------- conv + silu + l2norm + head transpose + gates (float4-vectorized) --------
__global__ void conv_gate(const float* __restrict__ cw, const float* __restrict__ dtb,
                          const float* __restrict__ Alog) {
    int bs = blockIdx.x;
    int b = bs / S_, s = bs % S_;
    int tid = threadIdx.x;
    __shared__ float cs[CONV_DIM];
    __shared__ float hsum[32];
    const float* base = g_qkvz + (size_t)bs * QKVZ_N;
    const float4* cw4 = (const float4*)cw;

    for (int c4 = tid; c4 < CONV_DIM / 4; c4 += 256) {
        int c = c4 * 4;
        float4 w0 = cw4[c + 0], w1 = cw4[c + 1], w2 = cw4[c + 2], w3 = cw4[c + 3];
        float4 x3 = *(const float4*)&base[c];
        float4 r;
        r.x = x3.x * w0.w; r.y = x3.y * w1.w; r.z = x3.z * w2.w; r.w = x3.w * w3.w;
        if (s >= 1) {
            float4 x2 = *(const float4*)&base[c - (size_t)QKVZ_N];
            r.x += x2.x * w0.z; r.y += x2.y * w1.z; r.z += x2.z * w2.z; r.w += x2.w * w3.z;
        }
        if (s >= 2) {
            float4 x1 = *(const float4*)&base[c - (size_t)2*QKVZ_N];
            r.x += x1.x * w0.y; r.y += x1.y * w1.y; r.z += x1.z * w2.y; r.w += x1.w * w3.y;
        }
        if (s >= 3) {
            float4 x0 = *(const float4*)&base[c - (size_t)3*QKVZ_N];
            r.x += x0.x * w0.x; r.y += x0.y * w1.x; r.z += x0.z * w2.x; r.w += x0.w * w3.x;
        }
        r.x = r.x / (1.f + __expf(-r.x));
        r.y = r.y / (1.f + __expf(-r.y));
        r.z = r.z / (1.f + __expf(-r.z));
        r.w = r.w / (1.f + __expf(-r.w));
        *(float4*)&cs[c] = r;
    }
    __syncthreads();
    int warp = tid >> 5, lane = tid & 31;
    for (int h = warp; h < 32; h += 8) {
        float ss = 0.f;
        for (int d = lane; d < 128; d += 32) { float v = cs[h*128 + d]; ss += v * v; }
#pragma unroll
        for (int o = 16; o; o >>= 1) ss += __shfl_xor_sync(~0u, ss, o);
        if (!lane) hsum[h] = rsqrtf(ss + 1e-6f);
    }
    __syncthreads();
    for (int c4 = tid; c4 < KEY_DIM / 4; c4 += 256) {
        int c = c4 * 4;
        int h = c >> 7, d = c & 127;
        float sc = hsum[h] * QSCALE;
        float4 v = *(float4*)&cs[c];
        v.x *= sc; v.y *= sc; v.z *= sc; v.w *= sc;
        *(float4*)&g_q[(((size_t)b*HKq + h)*S_ + s)*DKd + d] = v;
    }
    for (int c4 = tid; c4 < KEY_DIM / 4; c4 += 256) {
        int c = c4 * 4;
        int h = c >> 7, d = c & 127;
        float sc = hsum[16 + h];
        float4 v = *(float4*)&cs[KEY_DIM + c];
        v.x *= sc; v.y *= sc; v.z *= sc; v.w *= sc;
        *(float4*)&g_k[(((size_t)b*HKq + h)*S_ + s)*DKd + d] = v;
    }
    for (int c4 = tid; c4 < VALUE_DIM / 4; c4 += 256) {
        int c = c4 * 4;
        int h = c >> 7, d = c & 127;
        float4 v = *(float4*)&cs[2*KEY_DIM + c];
        *(float4*)&g_v[(((size_t)b*HVv + h)*S_ + s)*DVd + d] = v;
    }
    if (tid < 64) {
        float bb = g_ba[(size_t)bs * 64 + tid];
        if (tid < 32) {
            g_beta[((size_t)b*HVv + tid)*S_ + s] = 1.f / (1.f + expf(-bb));
        } else {
            int h = tid - 32;
            float a = bb + dtb[h];
            float sp = (a > 20.f) ? a : log1pf(expf(a));
            g_g[((size_t)b*HVv + h)*S_ + s] = -expf(Alog[h]) * sp;
        }
    }
}

// ======== chunk_prep: grid (b*hq*n)=1024; HMMA dots; dual-head T-solve ========
__global__ void __launch_bounds__(256, 1) chunk_prep() {
    extern __shared__ char smraw[];
    float* k_s   = (float*)smraw;
    float* vb_s  = k_s + 64*SW;
    float* dotsA = vb_s + 64*SW;
    float* dotsQ = dotsA + 4096;
    float* A2    = dotsQ + 4096;
    float* T2    = A2 + 8192;
    __half* k16  = (__half*)(T2 + 8320);
    __half* q16  = k16 + 64*SH6;
    __shared__ float gc2[2][64], beta2[2][64], kbe2[2][64];

    int blk = blockIdx.x;
    int n = blk & 31, hq = (blk >> 5) & 15, b = blk >> 9;
    int tid = threadIdx.x, lane = tid & 31, wid = tid >> 5;

    size_t qk_off = (((size_t)b*HKq + hq)*S_ + (size_t)n*CHUNK) * DKd;

    for (int idx = tid; idx < 2048; idx += 256) {
        int r = idx >> 5, d = (idx & 31) * 4;
        float4 qv = *(const float4*)&g_q[qk_off + (size_t)r*128 + d];
        float4 kv = *(const float4*)&g_k[qk_off + (size_t)r*128 + d];
        *(float4*)&k_s[r*SW + d] = kv;
        *(__half2*)&q16[r*SH6 + d]     = __floats2half2_rn(qv.x, qv.y);
        *(__half2*)&q16[r*SH6 + d + 2] = __floats2half2_rn(qv.z, qv.w);
        *(__half2*)&k16[r*SH6 + d]     = __floats2half2_rn(kv.x, kv.y);
        *(__half2*)&k16[r*SH6 + d + 2] = __floats2half2_rn(kv.z, kv.w);
    }
    if (tid < 128) {
        int hh = tid >> 6, i = tid & 63;
        size_t gb = ((size_t)b*HVv + hq*2 + hh)*S_ + (size_t)n*CHUNK;
        gc2[hh][i] = g_g[gb + i];
        beta2[hh][i] = g_beta[gb + i];
    }
    __syncthreads();
    if (tid < 2) {
        float* gcp = gc2[tid];
        for (int i = 1; i < 64; i++) gcp[i] += gcp[i - 1];
    }
    __syncthreads();
    if (tid < 128) {
        int hh = tid >> 6, i = tid & 63;
        size_t gb = ((size_t)b*HVv + hq*2 + hh)*S_ + (size_t)n*CHUNK;
        g_gc[gb + i] = gc2[hh][i];
        kbe2[hh][i] = beta2[hh][i] * expf(gc2[hh][i]);
    }

    {
        int mW = (wid >> 1) * 16, nW = (wid & 1) * 32;
        int g = lane >> 3, lr = lane & 7;
        uint32_t aK = smem_u32(k16) + 2u*(uint32_t)((mW + (g&1)*8 + lr)*SH6 + (g>>1)*8);
        uint32_t aQ = smem_u32(q16) + 2u*(uint32_t)((mW + (g&1)*8 + lr)*SH6 + (g>>1)*8);
        uint32_t bK = smem_u32(k16) + 2u*(uint32_t)((nW + (g>>1)*8 + lr)*SH6 + (g&1)*8);
        float accK[4][4], accQ[4][4];
#pragma unroll
        for (int i = 0; i < 4; i++)
#pragma unroll
            for (int r = 0; r < 4; r++) { accK[i][r] = 0.f; accQ[i][r] = 0.f; }
#pragma unroll
        for (int kt = 0; kt < 8; kt++) {
            uint32_t afk[4], afq[4], b0[4], b1[4];
            ldmx4(afk, aK + 2u*(kt*16));
            ldmx4(afq, aQ + 2u*(kt*16));
            ldmx4(b0, bK + 2u*(kt*16));
            ldmx4(b1, bK + 2u*(16*SH6 + kt*16));
            mma_f16(accK[0], afk, b0); mma_f16(accK[1], afk, b0 + 2);
            mma_f16(accK[2], afk, b1); mma_f16(accK[3], afk, b1 + 2);
            mma_f16(accQ[0], afq, b0); mma_f16(accQ[1], afq, b0 + 2);
            mma_f16(accQ[2], afq, b1); mma_f16(accQ[3], afq, b1 + 2);
        }
        int rr = lane >> 2, cc = (lane & 3) * 2;
#pragma unroll
        for (int ni = 0; ni < 4; ni++) {
            int j = nW + ni*8 + cc;
            int c0r = mW + rr;
            *(float2*)&dotsA[c0r*64 + j]     = make_float2(accK[ni][0], accK[ni][1]);
            *(float2*)&dotsA[(c0r+8)*64 + j] = make_float2(accK[ni][2], accK[ni][3]);
            *(float2*)&dotsQ[c0r*64 + j]     = make_float2(accQ[ni][0], accQ[ni][1]);
            *(float2*)&dotsQ[(c0r+8)*64 + j] = make_float2(accQ[ni][2], accQ[ni][3]);
        }
    }
    __syncthreads();

    for (int idx = tid; idx < 8192; idx += 256) {
        int hh = idx >> 12, i = idx & 4095;
        int c = i >> 6, j = i & 63;
        float e = __expf(gc2[hh][c] - gc2[hh][j]);
        A2[hh*4096 + i] = (j < c) ? dotsA[i] * beta2[hh][c] * e : 0.f;
        size_t at_off = (((size_t)b*HVv + hq*2 + hh)*S_ + (size_t)n*CHUNK) * CHUNK;
        g_attn[at_off + i] = (j <= c) ? dotsQ[i] * e : 0.f;
    }
    __syncthreads();

    if (tid < 128) {
        int hh = tid >> 6, col = tid & 63;
        float* A_s = A2 + hh*4096;
        float* T_s = T2 + hh*4160;
        for (int c = 0; c < 64; c++) {
            float ssum = (c == col) ? 1.f : 0.f;
            for (int j = col; j < c; j++) ssum -= A_s[c*64 + j] * T_s[j*65 + col];
            T_s[c*65 + col] = (c >= col) ? ssum : 0.f;
        }
    }
    __syncthreads();

#pragma unroll 1
    for (int h2 = 0; h2 < 2; h2++) {
        int h = hq * 2 + h2;
        size_t v_off  = (((size_t)b*HVv + h)*S_ + (size_t)n*CHUNK) * DVd;
        size_t gb_off = ((size_t)b*HVv + h)*S_ + (size_t)n*CHUNK;
        float* T_s = T2 + h2*4160;

        for (int idx = tid; idx < 2048; idx += 256) {
            int r = idx >> 5, d = (idx & 31) * 4;
            float4 vv = *(const float4*)&g_v[v_off + (size_t)r*128 + d];
            float be = beta2[h2][r];
            vv.x *= be; vv.y *= be; vv.z *= be; vv.w *= be;
            *(float4*)&vb_s[r*SW + d] = vv;
        }
        __syncthreads();

        {
            int ct8 = tid >> 5, lane2 = tid & 31;
            int c0 = ct8 * 8, d0 = lane2 * 4;
            float av[8][4] = {}, ak[8][4] = {};
            int jmax = c0 + 8;
            for (int j = 0; j < jmax; j++) {
                float4 vv = *(float4*)&vb_s[j*SW + d0];
                float4 kk = *(float4*)&k_s [j*SW + d0];
                float kb = kbe2[h2][j];
                kk.x *= kb; kk.y *= kb; kk.z *= kb; kk.w *= kb;
#pragma unroll
                for (int ci = 0; ci < 8; ci++) {
                    float t = T_s[(c0+ci)*65 + j];
                    av[ci][0] += t*vv.x; av[ci][1] += t*vv.y; av[ci][2] += t*vv.z; av[ci][3] += t*vv.w;
                    ak[ci][0] += t*kk.x; ak[ci][1] += t*kk.y; ak[ci][2] += t*kk.z; ak[ci][3] += t*kk.w;
                }
            }
            size_t kcd_off = gb_off * DKd;
#pragma unroll
            for (int ci = 0; ci < 8; ci++) {
                *(float4*)&g_vadj[v_off   + (size_t)(c0+ci)*128 + d0] =
                    make_float4(av[ci][0], av[ci][1], av[ci][2], av[ci][3]);
                *(float4*)&g_kcd [kcd_off + (size_t)(c0+ci)*128 + d0] =
                    make_float4(ak[ci][0], ak[ci][1], ak[ci][2], ak[ci][3]);
            }
        }
        __syncthreads();
    }
}

// ======== HMMA scan: state_T fp32 [dv][dk]; per-chunk fp16 operand tiles ========
__global__ void __launch_bounds__(512, 1) scan_kernel() {
    extern __shared__ char smraw[];
    float*  stT  = (float*)smraw;
    __half* st16 = (__half*)(stT + 64*STF);
    __half* kcd16= st16 + 64*SH6;
    __half* q16  = kcd16 + 64*SH6;
    __half* kT16 = q16 + 64*SH6;
    __half* at16 = kT16 + 128*SH7;
    __half* vnT16= at16 + 64*SH7;
    __half* vkT16= vnT16 + 64*SH7;
    __shared__ float eg_s[64], ek_s[64];

    int bh = blockIdx.x, dvt = blockIdx.y;
    int b = bh >> 5, h = bh & 31, hq = h >> 1;
    int tid = threadIdx.x, lane = tid & 31, wid = tid >> 5;

    int mW = (wid >> 2) * 16;
    int nW = (wid & 3) * 16;
    int g = lane >> 3, lr = lane & 7;
    int rr = lane >> 2, cc = (lane & 3) * 2;

    for (int i = tid; i < 64*STF; i += 512) stT[i] = 0.f;
    for (int i = tid; i < 64*SH6; i += 512) st16[i] = __float2half(0.f);

    uint32_t aKCD = smem_u32(kcd16) + 2u*((mW + (g&1)*8 + lr)*SH6 + (g>>1)*8);
    uint32_t aQ   = smem_u32(q16)   + 2u*((mW + (g&1)*8 + lr)*SH6 + (g>>1)*8);
    uint32_t aAT  = smem_u32(at16)  + 2u*((mW + (g&1)*8 + lr)*SH7 + (g>>1)*8);
    uint32_t bST  = smem_u32(st16)  + 2u*((nW + (g>>1)*8 + lr)*SH6 + (g&1)*8);
    uint32_t bVN  = smem_u32(vnT16) + 2u*((nW + (g>>1)*8 + lr)*SH7 + (g&1)*8);

    for (int n = 0; n < NCH; n++) {
        size_t qk_off = (((size_t)b*HKq + hq)*S_ + (size_t)n*CHUNK) * DKd;
        size_t kv_off = (((size_t)b*HVv + h )*S_ + (size_t)n*CHUNK) * DKd;
        size_t gb_off = ((size_t)b*HVv + h)*S_ + (size_t)n*CHUNK;

        __syncthreads();
        for (int idx = tid; idx < 2048; idx += 512) {
            int r = idx >> 5, d = (idx & 31) * 4;
            float4 kc = *(const float4*)&g_kcd[kv_off + (size_t)r*128 + d];
            float4 qv = *(const float4*)&g_q  [qk_off + (size_t)r*128 + d];
            float4 kv = *(const float4*)&g_k  [qk_off + (size_t)r*128 + d];
            *(__half2*)&kcd16[r*SH6 + d]     = __floats2half2_rn(-kc.x, -kc.y);
            *(__half2*)&kcd16[r*SH6 + d + 2] = __floats2half2_rn(-kc.z, -kc.w);
            *(__half2*)&q16[r*SH6 + d]       = __floats2half2_rn(qv.x, qv.y);
            *(__half2*)&q16[r*SH6 + d + 2]   = __floats2half2_rn(qv.z, qv.w);
            kT16[(d+0)*SH7 + r] = __float2half_rn(kv.x);
            kT16[(d+1)*SH7 + r] = __float2half_rn(kv.y);
            kT16[(d+2)*SH7 + r] = __float2half_rn(kv.z);
            kT16[(d+3)*SH7 + r] = __float2half_rn(kv.w);
        }
        for (int idx = tid; idx < 1024; idx += 512) {
            int c = idx >> 4, j = (idx & 15) * 4;
            float4 av = *(const float4*)&g_attn[gb_off*CHUNK + (size_t)c*64 + j];
            *(__half2*)&at16[c*SH7 + j]     = __floats2half2_rn(av.x, av.y);
            *(__half2*)&at16[c*SH7 + j + 2] = __floats2half2_rn(av.z, av.w);
        }
        if (tid < 64) {
            float gv = g_gc[gb_off + tid];
            float gl = g_gc[gb_off + 63];
            eg_s[tid] = expf(gv);
            ek_s[tid] = expf(gl - gv);
        }
        __syncthreads();

        // ---- M1 ----
        float c0[4], c1[4];
        {
            size_t vb = kv_off + (size_t)(mW + rr)*128 + dvt*64 + nW + cc;
            float2 t;
            t = *(const float2*)&g_vadj[vb];              c0[0]=t.x; c0[1]=t.y;
            t = *(const float2*)&g_vadj[vb + 8*128];      c0[2]=t.x; c0[3]=t.y;
            t = *(const float2*)&g_vadj[vb + 8];          c1[0]=t.x; c1[1]=t.y;
            t = *(const float2*)&g_vadj[vb + 8*128 + 8];  c1[2]=t.x; c1[3]=t.y;
        }
#pragma unroll
        for (int kt = 0; kt < 8; kt++) {
            uint32_t af[4], bf[4];
            ldmx4(af, aKCD + 2u*(kt*16));
            ldmx4(bf, bST  + 2u*(kt*16));
            mma_f16(c0, af, bf);
            mma_f16(c1, af, bf + 2);
        }
        {
            int cr0 = mW + rr, cr1 = mW + rr + 8;
            int d0 = nW + cc, d1 = nW + 8 + cc;
            float e0 = ek_s[cr0], e1 = ek_s[cr1];
            vnT16[(d0  )*SH7 + cr0] = __float2half_rn(c0[0]);
            vnT16[(d0+1)*SH7 + cr0] = __float2half_rn(c0[1]);
            vnT16[(d0  )*SH7 + cr1] = __float2half_rn(c0[2]);
            vnT16[(d0+1)*SH7 + cr1] = __float2half_rn(c0[3]);
            vnT16[(d1  )*SH7 + cr0] = __float2half_rn(c1[0]);
            vnT16[(d1+1)*SH7 + cr0] = __float2half_rn(c1[1]);
            vnT16[(d1  )*SH7 + cr1] = __float2half_rn(c1[2]);
            vnT16[(d1+1)*SH7 + cr1] = __float2half_rn(c1[3]);
            vkT16[(d0  )*SH7 + cr0] = __float2half_rn(c0[0]*e0);
            vkT16[(d0+1)*SH7 + cr0] = __float2half_rn(c0[1]*e0);
            vkT16[(d0  )*SH7 + cr1] = __float2half_rn(c0[2]*e1);
            vkT16[(d0+1)*SH7 + cr1] = __float2half_rn(c0[3]*e1);
            vkT16[(d1  )*SH7 + cr0] = __float2half_rn(c1[0]*e0);
            vkT16[(d1+1)*SH7 + cr0] = __float2half_rn(c1[1]*e0);
            vkT16[(d1  )*SH7 + cr1] = __float2half_rn(c1[2]*e1);
            vkT16[(d1+1)*SH7 + cr1] = __float2half_rn(c1[3]*e1);
        }
        __syncthreads();

        // ---- M2 ----
        float o0[4] = {0,0,0,0}, o1[4] = {0,0,0,0};
#pragma unroll
        for (int kt = 0; kt < 8; kt++) {
            uint32_t af[4], bf[4];
            ldmx4(af, aQ  + 2u*(kt*16));
            ldmx4(bf, bST + 2u*(kt*16));
            mma_f16(o0, af, bf);
            mma_f16(o1, af, bf + 2);
        }
        {
            float e0 = eg_s[mW + rr], e1 = eg_s[mW + rr + 8];
            o0[0]*=e0; o0[1]*=e0; o0[2]*=e1; o0[3]*=e1;
            o1[0]*=e0; o1[1]*=e0; o1[2]*=e1; o1[3]*=e1;
        }
#pragma unroll
        for (int kt = 0; kt < 4; kt++) {
            uint32_t af[4], bf[4];
            ldmx4(af, aAT + 2u*(kt*16));
            ldmx4(bf, bVN + 2u*(kt*16));
            mma_f16(o0, af, bf);
            mma_f16(o1, af, bf + 2);
        }
        {
            size_t ob = ((size_t)b*S_ + (size_t)n*CHUNK + mW + rr)*VALUE_DIM
                      + (size_t)h*DVd + dvt*64 + nW + cc;
            *(float2*)&g_o[ob]                       = make_float2(o0[0], o0[1]);
            *(float2*)&g_o[ob + 8*(size_t)VALUE_DIM] = make_float2(o0[2], o0[3]);
            *(float2*)&g_o[ob + 8]                   = make_float2(o1[0], o1[1]);
            *(float2*)&g_o[ob + 8*(size_t)VALUE_DIM + 8] = make_float2(o1[2], o1[3]);
        }
        __syncthreads();

        // ---- M3 ----
        float egl = eg_s[63];
#pragma unroll
        for (int i = 0; i < 2; i++) {
            int t = wid * 2 + i;
            int dv0 = (t >> 3) * 16, dk0 = (t & 7) * 16;
            float s0[4], s1[4];
            float* sp  = &stT[(dv0 + rr)*STF + dk0 + cc];
            float* sp8 = &stT[(dv0 + rr + 8)*STF + dk0 + cc];
            s0[0] = sp[0]*egl;  s0[1] = sp[1]*egl;
            s1[0] = sp[8]*egl;  s1[1] = sp[9]*egl;
            s0[2] = sp8[0]*egl; s0[3] = sp8[1]*egl;
            s1[2] = sp8[8]*egl; s1[3] = sp8[9]*egl;
            uint32_t aV = smem_u32(vkT16) + 2u*((dv0 + (g&1)*8 + lr)*SH7 + (g>>1)*8);
            uint32_t bK = smem_u32(kT16)  + 2u*((dk0 + (g>>1)*8 + lr)*SH7 + (g&1)*8);
#pragma unroll
            for (int kt = 0; kt < 4; kt++) {
                uint32_t af[4], bf[4];
                ldmx4(af, aV + 2u*(kt*16));
                ldmx4(bf, bK + 2u*(kt*16));
                mma_f16(s0, af, bf);
                mma_f16(s1, af, bf + 2);
            }
            sp[0]=s0[0];  sp[1]=s0[1];  sp[8]=s1[0];  sp[9]=s1[1];
            sp8[0]=s0[2]; sp8[1]=s0[3]; sp8[8]=s1[2]; sp8[9]=s1[3];
            *(__half2*)&st16[(dv0+rr)*SH6 + dk0 + cc]       = __floats2half2_rn(s0[0], s0[1]);
            *(__half2*)&st16[(dv0+rr)*SH6 + dk0 + 8 + cc]   = __floats2half2_rn(s1[0], s1[1]);
            *(__half2*)&st16[(dv0+rr+8)*SH6 + dk0 + cc]     = __floats2half2_rn(s0[2], s0[3]);
            *(__half2*)&st16[(dv0+rr+8)*SH6 + dk0 + 8 + cc] = __floats2half2_rn(s1[2], s1[3]);
        }
    }
}

// -------- gated RMSNorm -> fp16 directly into GEMM2 A buffer --------
__global__ void gated_norm(const float* __restrict__ nw) {
    int bs = blockIdx.x;
    int warp = threadIdx.x >> 5, lane = threadIdx.x & 31;
    for (int h = warp; h < HVv; h += 8) {
        size_t off = (size_t)bs * VALUE_DIM + (size_t)h * DVd;
        float4 v = ((float4*)(g_o + off))[lane];
        float ss = v.x*v.x + v.y*v.y + v.z*v.z + v.w*v.w;
#pragma unroll
        for (int o = 16; o; o >>= 1) ss += __shfl_xor_sync(~0u, ss, o);
        float r = rsqrtf(ss / 128.f + 1e-6f);
        size_t zoff = (size_t)bs * QKVZ_N + 2*KEY_DIM + VALUE_DIM + (size_t)h * DVd;
        float4 z = ((const float4*)(g_qkvz + zoff))[lane];
        float4 w = ((const float4*)nw)[lane];
        float r0 = v.x * r * w.x * (z.x / (1.f + expf(-z.x)));
        float r1 = v.y * r * w.y * (z.y / (1.f + expf(-z.y)));
        float r2 = v.z * r * w.z * (z.z / (1.f + expf(-z.z)));
        float r3 = v.w * r * w.w * (z.w / (1.f + expf(-z.w)));
        __half2 h0 = __floats2half2_rn(r0, r1);
        __half2 h1 = __floats2half2_rn(r2, r3);
        uint2 hv; hv.x = *(uint32_t*)&h0; hv.y = *(uint32_t*)&h1;
        ((uint2*)(g_r + off))[lane] = hv;
    }
}

// ---------------- launcher (single stream) ----------------
extern "C" void kernel_launch(void* const* d_in, const int* in_sizes, int n_in,
                              void* d_out, int out_size) {
    const float* hidden = (const float*)d_in[0];
    const float* Wqkvz  = (const float*)d_in[1];
    const float* Wba    = (const float*)d_in[2];
    const float* convw  = (const float*)d_in[3];
    const float* dtb    = (const float*)d_in[4];
    const float* Alog   = (const float*)d_in[5];
    const float* nw     = (const float*)d_in[6];
    const float* Wout   = (const float*)d_in[7];
    float* out = (float*)d_out;

    float *qkvz_p;
    __half *p_p, *r_p, *wba_p;
    cudaGetSymbolAddress((void**)&qkvz_p, g_qkvz);
    cudaGetSymbolAddress((void**)&p_p, g_p);
    cudaGetSymbolAddress((void**)&r_p, g_r);
    cudaGetSymbolAddress((void**)&wba_p, g_wba);

    const int SMEM3 = (2*64*SW + 2*4096 + 2*4096 + 2*64*65) * 4 + 2*64*SH6 * 2;
    const int SMEM4 = 64*STF*4 + (3*64*SH6 + 128*SH7 + 3*64*SH7) * 2;
    const int SMEM_MM = NSTG * STG1 * 2;
    cudaFuncSetAttribute(chunk_prep, cudaFuncAttributeMaxDynamicSharedMemorySize, SMEM3);
    cudaFuncSetAttribute(scan_kernel, cudaFuncAttributeMaxDynamicSharedMemorySize, SMEM4);
    cudaFuncSetAttribute(mmgemm, cudaFuncAttributeMaxDynamicSharedMemorySize, SMEM_MM);

    // --- operand conversions ---
    cvt_h<<<(BSz*(size_t)HID)/1024, 256>>>(hidden, p_p);
    cvt_T<<<dim3(QKVZ_N/32, HID/32), dim3(32,8)>>>(Wqkvz, r_p, HID, QKVZ_N);
    cvt_T<<<dim3(2, HID/32), dim3(32,8)>>>(Wba, wba_p, HID, 64);

    // --- GEMM1: qkvz = hidden @ W_qkvz ---
    mmgemm<<<dim3(BSz/128, QKVZ_N/128), 256, SMEM_MM>>>(p_p, r_p, qkvz_p, BSz, QKVZ_N, HID);

    // --- BA projection (HMMA) ---
    gemm_ba_h<<<BSz/32, 256>>>(p_p);

    // --- conv + gates, chunk prep, scan, norm ---
    conv_gate<<<BSz, 256>>>(convw, dtb, Alog);
    chunk_prep<<<B_*HKq*NCH, 256, SMEM3>>>();
    scan_kernel<<<dim3(B_*HVv, 2), 512, SMEM4>>>();
    gated_norm<<<BSz, 256>>>(nw);

    // --- GEMM2: out = o @ W_out ---
    cvt_T<<<dim3(HID/32, VALUE_DIM/32), dim3(32,8)>>>(Wout, p_p, VALUE_DIM, HID);
    mmgemm<<<dim3(BSz/128, HID/128), 256, SMEM_MM>>>(r_p, p_p, out, BSz, HID, VALUE_DIM);
}

// round 17
// speedup vs baseline: 1.0763x; 1.0547x over previous
#include <cuda_runtime.h>
#include <cuda_bf16.h>
#include <cuda_fp16.h>
#include <math.h>
#include <stdint.h>

// ---------------- problem constants ----------------
#define B_   2
#define S_   2048
#define HID  2048
#define HKq  16
#define HVv  32
#define DKd  128
#define DVd  128
#define KC   4
#define CHUNK 64
#define NCH  (S_/CHUNK)          // 32
#define KEY_DIM 2048
#define VALUE_DIM 4096
#define CONV_DIM 8192
#define QKVZ_N 12288
#define BSz  (B_*S_)             // 4096
#define QSCALE 0.08838834764831845f   // DK^-0.5
#define SW 132
#define STF 132
#define SH6 136
#define SH7 72

// ---------------- scratch (static device memory; no allocations) ------------
__device__ float g_qkvz[(size_t)BSz*QKVZ_N];
__device__ float g_ba[(size_t)BSz*64];
__device__ float g_k[(size_t)B_*HKq*S_*DKd];
__device__ float g_v[(size_t)B_*HVv*S_*DVd];
__device__ float g_g[(size_t)B_*HVv*S_];
__device__ float g_beta[(size_t)B_*HVv*S_];
__device__ float g_gc[(size_t)B_*HVv*S_];
__device__ float g_vadj[(size_t)B_*HVv*S_*DVd];
__device__ float g_o[(size_t)BSz*VALUE_DIM];

__device__ __align__(16) __half g_p [(size_t)8388608];    // A1 (hidden) / B2t (Wout^T)
__device__ __align__(16) __half g_r [(size_t)25165824];   // B1t (Wqkvz^T) ; later A2
__device__ __align__(16) __half g_wba[(size_t)64*2048];   // W_ba^T fp16
__device__ __align__(16) __half g_q16  [(size_t)B_*HKq*S_*DKd];      // q fp16 (scaled)
__device__ __align__(16) __half g_kcd16[(size_t)B_*HVv*S_*DKd];      // -kcd fp16
__device__ __align__(16) __half g_kT16 [(size_t)B_*HKq*NCH*128*64];  // k^T fp16 per chunk
__device__ __align__(16) __half g_attn16[(size_t)B_*HVv*S_*CHUNK];   // attn fp16

__device__ __forceinline__ uint32_t smem_u32(const void* p) {
    uint32_t a;
    asm("{ .reg .u64 t; cvta.to.shared.u64 t, %1; cvt.u32.u64 %0, t; }" : "=r"(a) : "l"(p));
    return a;
}

// ---------------- fp32 -> fp16 (elementwise, float4) ----------------
__global__ void cvt_h(const float* __restrict__ X, __half* __restrict__ H) {
    size_t i = ((size_t)blockIdx.x * 256 + threadIdx.x) * 4;
    float4 v = *(const float4*)&X[i];
    __half2 h0 = __floats2half2_rn(v.x, v.y);
    __half2 h1 = __floats2half2_rn(v.z, v.w);
    uint2 hv;
    hv.x = *(uint32_t*)&h0; hv.y = *(uint32_t*)&h1;
    *(uint2*)&H[i] = hv;
}

// ---------------- fp32 [K,N] -> fp16 [N,K] transpose ----------------
__global__ void cvt_T(const float* __restrict__ W, __half* __restrict__ Ht, int K, int N) {
    __shared__ float tile[32][33];
    int n0 = blockIdx.x * 32, k0 = blockIdx.y * 32;
    int tx = threadIdx.x, ty = threadIdx.y;
#pragma unroll
    for (int j = 0; j < 32; j += 8)
        tile[ty + j][tx] = W[(size_t)(k0 + ty + j) * N + n0 + tx];
    __syncthreads();
#pragma unroll
    for (int j = 0; j < 32; j += 8)
        Ht[(size_t)(n0 + ty + j) * K + k0 + tx] = __float2half_rn(tile[tx][ty + j]);
}

// ============ fp16 HMMA GEMM (R14 structure) ============
#define PSH 40
#define TEN2 (128*PSH)
#define STG1 (2*TEN2)
#define NSTG 4

__device__ __forceinline__ void mma_f16(float* c, const uint32_t* a, const uint32_t* b) {
    asm volatile("mma.sync.aligned.m16n8k16.row.col.f32.f16.f16.f32 "
                 "{%0,%1,%2,%3}, {%4,%5,%6,%7}, {%8,%9}, {%0,%1,%2,%3};"
                 : "+f"(c[0]), "+f"(c[1]), "+f"(c[2]), "+f"(c[3])
                 : "r"(a[0]), "r"(a[1]), "r"(a[2]), "r"(a[3]), "r"(b[0]), "r"(b[1]));
}
__device__ __forceinline__ void ldmx4(uint32_t* r, uint32_t addr) {
    asm volatile("ldmatrix.sync.aligned.m8n8.x4.shared.b16 {%0,%1,%2,%3}, [%4];"
                 : "=r"(r[0]), "=r"(r[1]), "=r"(r[2]), "=r"(r[3]) : "r"(addr));
}

__device__ __forceinline__ void stage_load(uint32_t sbase_b, int stage,
    const __half* a0, const __half* b0, int K, int kt, int tid)
{
    const __half* gp[2] = {a0, b0};
    uint32_t st_b = sbase_b + (uint32_t)stage * (STG1 * 2);
#pragma unroll
    for (int t = 0; t < 2; t++) {
        uint32_t tb = st_b + (uint32_t)t * (TEN2 * 2);
#pragma unroll
        for (int j = 0; j < 2; j++) {
            int idx = j * 256 + tid;
            int row = idx >> 2, c16 = idx & 3;
            uint32_t sa = tb + (uint32_t)(row * (PSH*2) + c16 * 16);
            const void* ga = gp[t] + (size_t)row * K + (size_t)kt * 32 + c16 * 8;
            asm volatile("cp.async.cg.shared.global [%0], [%1], 16;" :: "r"(sa), "l"(ga));
        }
    }
    asm volatile("cp.async.commit_group;" ::: "memory");
}

__global__ void __launch_bounds__(256, 2) mmgemm(
    const __half* __restrict__ Ah, const __half* __restrict__ Bh,
    float* __restrict__ C, int M, int N, int K)
{
    extern __shared__ __half smem[];
    uint32_t sbase = smem_u32(smem);
    int tid = threadIdx.x, lane = tid & 31, wid = tid >> 5;
    int warpM = wid >> 2, warpN = wid & 3;
    int bm = blockIdx.x, bn = blockIdx.y;
    const int T = K >> 5;

    const __half* a0 = Ah + (size_t)bm * 128 * K;
    const __half* b0 = Bh + (size_t)bn * 128 * K;

    int g = lane >> 3, lr = lane & 7;
    uint32_t aoff = (uint32_t)((warpM*64 + (g&1)*8 + lr) * PSH + (g>>1)*8);
    uint32_t boff = (uint32_t)((warpN*32 + (g>>1)*8 + lr) * PSH + (g&1)*8);

    float acc[4][4][4];
#pragma unroll
    for (int i = 0; i < 4; i++)
#pragma unroll
        for (int j = 0; j < 4; j++)
#pragma unroll
            for (int r = 0; r < 4; r++) acc[i][j][r] = 0.f;

    stage_load(sbase, 0, a0, b0, K, 0, tid);
    stage_load(sbase, 1, a0, b0, K, 1, tid);
    stage_load(sbase, 2, a0, b0, K, 2, tid);

    for (int kt = 0; kt < T; kt++) {
        int rem = T - 1 - kt;
        if (rem >= 2)      asm volatile("cp.async.wait_group 2;" ::: "memory");
        else if (rem == 1) asm volatile("cp.async.wait_group 1;" ::: "memory");
        else               asm volatile("cp.async.wait_group 0;" ::: "memory");
        __syncthreads();
        if (kt + 3 < T) stage_load(sbase, (kt + 3) % NSTG, a0, b0, K, kt + 3, tid);

        uint32_t st = sbase + (uint32_t)(kt % NSTG) * (STG1 * 2);
        uint32_t sA = st, sB = st + TEN2*2;
#pragma unroll
        for (int ks = 0; ks < 2; ks++) {
            int kk = ks * 16;
            uint32_t ah[4][4], bh[4][2];
#pragma unroll
            for (int mi = 0; mi < 4; mi++)
                ldmx4(ah[mi], sA + (aoff + mi*16*PSH + kk) * 2);
#pragma unroll
            for (int p = 0; p < 2; p++) {
                uint32_t rh[4];
                ldmx4(rh, sB + (boff + p*16*PSH + kk) * 2);
                bh[2*p][0] = rh[0]; bh[2*p][1] = rh[1];
                bh[2*p+1][0] = rh[2]; bh[2*p+1][1] = rh[3];
            }
#pragma unroll
            for (int mi = 0; mi < 4; mi++)
#pragma unroll
                for (int ni = 0; ni < 4; ni++)
                    mma_f16(acc[mi][ni], ah[mi], bh[ni]);
        }
        __syncthreads();
    }

    int rr = lane >> 2, cc = (lane & 3) * 2;
#pragma unroll
    for (int mi = 0; mi < 4; mi++) {
        int row0 = bm * 128 + warpM * 64 + mi * 16 + rr;
#pragma unroll
        for (int ni = 0; ni < 4; ni++) {
            int col = bn * 128 + warpN * 32 + ni * 8 + cc;
            float2 v0 = make_float2(acc[mi][ni][0], acc[mi][ni][1]);
            float2 v1 = make_float2(acc[mi][ni][2], acc[mi][ni][3]);
            *(float2*)&C[(size_t)row0 * N + col]       = v0;
            *(float2*)&C[(size_t)(row0 + 8) * N + col] = v1;
        }
    }
}

// ------------- BA projection, HMMA -------------
__global__ void __launch_bounds__(256) gemm_ba_h(const __half* __restrict__ A) {
    __shared__ __half As[2][32*SH7];
    __shared__ __half Bs[2][64*SH7];
    int tid = threadIdx.x, lane = tid & 31, wid = tid >> 5;
    int bm = blockIdx.x;
    int wm = wid >> 2, wn = wid & 3;
    int g = lane >> 3, lr = lane & 7;
    const __half* Ab = A + (size_t)bm * 32 * 2048;

    uint32_t aoff = (uint32_t)((wm*16 + (g&1)*8 + lr) * SH7 + (g>>1)*8);
    uint32_t boff = (uint32_t)((wn*16 + (g>>1)*8 + lr) * SH7 + (g&1)*8);
    uint32_t asA[2] = { smem_u32(As[0]), smem_u32(As[1]) };
    uint32_t asB[2] = { smem_u32(Bs[0]), smem_u32(Bs[1]) };

    float acc[2][4] = {};

    auto ld = [&](int st, int kt) {
        {
            int row = tid >> 3, ch = tid & 7;
            uint32_t dst = asA[st] + (uint32_t)(row*SH7 + ch*8) * 2;
            const void* src = Ab + (size_t)row*2048 + kt*64 + ch*8;
            asm volatile("cp.async.cg.shared.global [%0], [%1], 16;" :: "r"(dst), "l"(src));
        }
#pragma unroll
        for (int j = 0; j < 2; j++) {
            int idx = j*256 + tid;
            int row = idx >> 3, ch = idx & 7;
            uint32_t dst = asB[st] + (uint32_t)(row*SH7 + ch*8) * 2;
            const void* src = g_wba + (size_t)row*2048 + kt*64 + ch*8;
            asm volatile("cp.async.cg.shared.global [%0], [%1], 16;" :: "r"(dst), "l"(src));
        }
        asm volatile("cp.async.commit_group;" ::: "memory");
    };

    ld(0, 0);
    for (int kt = 0; kt < 32; kt++) {
        if (kt + 1 < 32) {
            ld((kt + 1) & 1, kt + 1);
            asm volatile("cp.async.wait_group 1;" ::: "memory");
        } else {
            asm volatile("cp.async.wait_group 0;" ::: "memory");
        }
        __syncthreads();
        int st = kt & 1;
#pragma unroll
        for (int ks = 0; ks < 4; ks++) {
            uint32_t af[4], bf[4];
            ldmx4(af, asA[st] + (aoff + ks*16) * 2);
            ldmx4(bf, asB[st] + (boff + ks*16) * 2);
            mma_f16(acc[0], af, bf);
            mma_f16(acc[1], af, bf + 2);
        }
        __syncthreads();
    }

    int rr = lane >> 2, cc = (lane & 3) * 2;
    int row0 = bm * 32 + wm * 16 + rr;
#pragma unroll
    for (int ni = 0; ni < 2; ni++) {
        int col = wn * 16 + ni * 8 + cc;
        *(float2*)&g_ba[(size_t)row0 * 64 + col]       = make_float2(acc[ni][0], acc[ni][1]);
        *(float2*)&g_ba[(size_t)(row0 + 8) * 64 + col] = make_float2(acc[ni][2], acc[ni][3]);
    }
}

// -------- conv + silu + l2norm + transpose + gates; q emitted fp16 --------
__global__ void conv_gate(const float* __restrict__ cw, const float* __restrict__ dtb,
                          const float* __restrict__ Alog) {
    int bs = blockIdx.x;
    int b = bs / S_, s = bs % S_;
    int tid = threadIdx.x;
    __shared__ float cs[CONV_DIM];
    __shared__ float hsum[32];
    const float* base = g_qkvz + (size_t)bs * QKVZ_N;
    const float4* cw4 = (const float4*)cw;

    for (int c4 = tid; c4 < CONV_DIM / 4; c4 += 256) {
        int c = c4 * 4;
        float4 w0 = cw4[c + 0], w1 = cw4[c + 1], w2 = cw4[c + 2], w3 = cw4[c + 3];
        float4 x3 = *(const float4*)&base[c];
        float4 r;
        r.x = x3.x * w0.w; r.y = x3.y * w1.w; r.z = x3.z * w2.w; r.w = x3.w * w3.w;
        if (s >= 1) {
            float4 x2 = *(const float4*)&base[c - (size_t)QKVZ_N];
            r.x += x2.x * w0.z; r.y += x2.y * w1.z; r.z += x2.z * w2.z; r.w += x2.w * w3.z;
        }
        if (s >= 2) {
            float4 x1 = *(const float4*)&base[c - (size_t)2*QKVZ_N];
            r.x += x1.x * w0.y; r.y += x1.y * w1.y; r.z += x1.z * w2.y; r.w += x1.w * w3.y;
        }
        if (s >= 3) {
            float4 x0 = *(const float4*)&base[c - (size_t)3*QKVZ_N];
            r.x += x0.x * w0.x; r.y += x0.y * w1.x; r.z += x0.z * w2.x; r.w += x0.w * w3.x;
        }
        r.x = r.x / (1.f + __expf(-r.x));
        r.y = r.y / (1.f + __expf(-r.y));
        r.z = r.z / (1.f + __expf(-r.z));
        r.w = r.w / (1.f + __expf(-r.w));
        *(float4*)&cs[c] = r;
    }
    __syncthreads();
    int warp = tid >> 5, lane = tid & 31;
    for (int h = warp; h < 32; h += 8) {
        float ss = 0.f;
        for (int d = lane; d < 128; d += 32) { float v = cs[h*128 + d]; ss += v * v; }
#pragma unroll
        for (int o = 16; o; o >>= 1) ss += __shfl_xor_sync(~0u, ss, o);
        if (!lane) hsum[h] = rsqrtf(ss + 1e-6f);
    }
    __syncthreads();
    for (int c4 = tid; c4 < KEY_DIM / 4; c4 += 256) {
        int c = c4 * 4;
        int h = c >> 7, d = c & 127;
        float sc = hsum[h] * QSCALE;
        float4 v = *(float4*)&cs[c];
        v.x *= sc; v.y *= sc; v.z *= sc; v.w *= sc;
        __half2 h0 = __floats2half2_rn(v.x, v.y);
        __half2 h1 = __floats2half2_rn(v.z, v.w);
        uint2 hv; hv.x = *(uint32_t*)&h0; hv.y = *(uint32_t*)&h1;
        *(uint2*)&g_q16[(((size_t)b*HKq + h)*S_ + s)*DKd + d] = hv;
    }
    for (int c4 = tid; c4 < KEY_DIM / 4; c4 += 256) {
        int c = c4 * 4;
        int h = c >> 7, d = c & 127;
        float sc = hsum[16 + h];
        float4 v = *(float4*)&cs[KEY_DIM + c];
        v.x *= sc; v.y *= sc; v.z *= sc; v.w *= sc;
        *(float4*)&g_k[(((size_t)b*HKq + h)*S_ + s)*DKd + d] = v;
    }
    for (int c4 = tid; c4 < VALUE_DIM / 4; c4 += 256) {
        int c = c4 * 4;
        int h = c >> 7, d = c & 127;
        float4 v = *(float4*)&cs[2*KEY_DIM + c];
        *(float4*)&g_v[(((size_t)b*HVv + h)*S_ + s)*DVd + d] = v;
    }
    if (tid < 64) {
        float bb = g_ba[(size_t)bs * 64 + tid];
        if (tid < 32) {
            g_beta[((size_t)b*HVv + tid)*S_ + s] = 1.f / (1.f + expf(-bb));
        } else {
            int h = tid - 32;
            float a = bb + dtb[h];
            float sp = (a > 20.f) ? a : log1pf(expf(a));
            g_g[((size_t)b*HVv + h)*S_ + s] = -expf(Alog[h]) * sp;
        }
    }
}

// ======== chunk_prep: HMMA dots; dual-head T-solve; fp16 outputs for scan ========
__global__ void __launch_bounds__(256, 1) chunk_prep() {
    extern __shared__ char smraw[];
    float* k_s   = (float*)smraw;
    float* vb_s  = k_s + 64*SW;
    float* dotsA = vb_s + 64*SW;
    float* dotsQ = dotsA + 4096;
    float* A2    = dotsQ + 4096;
    float* T2    = A2 + 8192;
    __half* k16  = (__half*)(T2 + 8320);
    __half* q16  = k16 + 64*SH6;
    __shared__ float gc2[2][64], beta2[2][64], kbe2[2][64];

    int blk = blockIdx.x;
    int n = blk & 31, hq = (blk >> 5) & 15, b = blk >> 9;
    int tid = threadIdx.x, lane = tid & 31, wid = tid >> 5;

    size_t qk_off = (((size_t)b*HKq + hq)*S_ + (size_t)n*CHUNK) * DKd;

    for (int idx = tid; idx < 2048; idx += 256) {
        int r = idx >> 5, d = (idx & 31) * 4;
        float4 kv = *(const float4*)&g_k[qk_off + (size_t)r*128 + d];
        *(float4*)&k_s[r*SW + d] = kv;
        *(__half2*)&k16[r*SH6 + d]     = __floats2half2_rn(kv.x, kv.y);
        *(__half2*)&k16[r*SH6 + d + 2] = __floats2half2_rn(kv.z, kv.w);
    }
    for (int idx = tid; idx < 1024; idx += 256) {
        int r = idx >> 4, c = (idx & 15) * 8;
        *(uint4*)&q16[r*SH6 + c] = *(const uint4*)&g_q16[qk_off + (size_t)r*128 + c];
    }
    if (tid < 128) {
        int hh = tid >> 6, i = tid & 63;
        size_t gb = ((size_t)b*HVv + hq*2 + hh)*S_ + (size_t)n*CHUNK;
        gc2[hh][i] = g_g[gb + i];
        beta2[hh][i] = g_beta[gb + i];
    }
    __syncthreads();
    if (tid < 2) {
        float* gcp = gc2[tid];
        for (int i = 1; i < 64; i++) gcp[i] += gcp[i - 1];
    }
    // write k^T fp16 for scan (k_s ready after the barrier above)
    {
        size_t ktb = (((size_t)b*HKq + hq)*(size_t)NCH + n) * (128*64);
        for (int idx = tid; idx < 2048; idx += 256) {
            int dk = idx >> 4, c4 = (idx & 15) * 4;
            __half2 h0 = __floats2half2_rn(k_s[(c4+0)*SW + dk], k_s[(c4+1)*SW + dk]);
            __half2 h1 = __floats2half2_rn(k_s[(c4+2)*SW + dk], k_s[(c4+3)*SW + dk]);
            uint2 u; u.x = *(uint32_t*)&h0; u.y = *(uint32_t*)&h1;
            *(uint2*)&g_kT16[ktb + (size_t)dk*64 + c4] = u;
        }
    }
    __syncthreads();
    if (tid < 128) {
        int hh = tid >> 6, i = tid & 63;
        size_t gb = ((size_t)b*HVv + hq*2 + hh)*S_ + (size_t)n*CHUNK;
        g_gc[gb + i] = gc2[hh][i];
        kbe2[hh][i] = beta2[hh][i] * expf(gc2[hh][i]);
    }

    {
        int mW = (wid >> 1) * 16, nW = (wid & 1) * 32;
        int g = lane >> 3, lr = lane & 7;
        uint32_t aK = smem_u32(k16) + 2u*(uint32_t)((mW + (g&1)*8 + lr)*SH6 + (g>>1)*8);
        uint32_t aQ = smem_u32(q16) + 2u*(uint32_t)((mW + (g&1)*8 + lr)*SH6 + (g>>1)*8);
        uint32_t bK = smem_u32(k16) + 2u*(uint32_t)((nW + (g>>1)*8 + lr)*SH6 + (g&1)*8);
        float accK[4][4], accQ[4][4];
#pragma unroll
        for (int i = 0; i < 4; i++)
#pragma unroll
            for (int r = 0; r < 4; r++) { accK[i][r] = 0.f; accQ[i][r] = 0.f; }
#pragma unroll
        for (int kt = 0; kt < 8; kt++) {
            uint32_t afk[4], afq[4], b0[4], b1[4];
            ldmx4(afk, aK + 2u*(kt*16));
            ldmx4(afq, aQ + 2u*(kt*16));
            ldmx4(b0, bK + 2u*(kt*16));
            ldmx4(b1, bK + 2u*(16*SH6 + kt*16));
            mma_f16(accK[0], afk, b0); mma_f16(accK[1], afk, b0 + 2);
            mma_f16(accK[2], afk, b1); mma_f16(accK[3], afk, b1 + 2);
            mma_f16(accQ[0], afq, b0); mma_f16(accQ[1], afq, b0 + 2);
            mma_f16(accQ[2], afq, b1); mma_f16(accQ[3], afq, b1 + 2);
        }
        int rr = lane >> 2, cc = (lane & 3) * 2;
#pragma unroll
        for (int ni = 0; ni < 4; ni++) {
            int j = nW + ni*8 + cc;
            int c0r = mW + rr;
            *(float2*)&dotsA[c0r*64 + j]     = make_float2(accK[ni][0], accK[ni][1]);
            *(float2*)&dotsA[(c0r+8)*64 + j] = make_float2(accK[ni][2], accK[ni][3]);
            *(float2*)&dotsQ[c0r*64 + j]     = make_float2(accQ[ni][0], accQ[ni][1]);
            *(float2*)&dotsQ[(c0r+8)*64 + j] = make_float2(accQ[ni][2], accQ[ni][3]);
        }
    }
    __syncthreads();

    for (int idx = tid; idx < 8192; idx += 256) {
        int hh = idx >> 12, i = idx & 4095;
        int c = i >> 6, j = i & 63;
        float e = __expf(gc2[hh][c] - gc2[hh][j]);
        A2[hh*4096 + i] = (j < c) ? dotsA[i] * beta2[hh][c] * e : 0.f;
        size_t at_off = (((size_t)b*HVv + hq*2 + hh)*S_ + (size_t)n*CHUNK) * CHUNK;
        float av = (j <= c) ? dotsQ[i] * e : 0.f;
        g_attn16[at_off + i] = __float2half_rn(av);
    }
    __syncthreads();

    if (tid < 128) {
        int hh = tid >> 6, col = tid & 63;
        float* A_s = A2 + hh*4096;
        float* T_s = T2 + hh*4160;
        for (int c = 0; c < 64; c++) {
            float ssum = (c == col) ? 1.f : 0.f;
            for (int j = col; j < c; j++) ssum -= A_s[c*64 + j] * T_s[j*65 + col];
            T_s[c*65 + col] = (c >= col) ? ssum : 0.f;
        }
    }
    __syncthreads();

#pragma unroll 1
    for (int h2 = 0; h2 < 2; h2++) {
        int h = hq * 2 + h2;
        size_t v_off  = (((size_t)b*HVv + h)*S_ + (size_t)n*CHUNK) * DVd;
        size_t gb_off = ((size_t)b*HVv + h)*S_ + (size_t)n*CHUNK;
        float* T_s = T2 + h2*4160;

        for (int idx = tid; idx < 2048; idx += 256) {
            int r = idx >> 5, d = (idx & 31) * 4;
            float4 vv = *(const float4*)&g_v[v_off + (size_t)r*128 + d];
            float be = beta2[h2][r];
            vv.x *= be; vv.y *= be; vv.z *= be; vv.w *= be;
            *(float4*)&vb_s[r*SW + d] = vv;
        }
        __syncthreads();

        {
            int ct8 = tid >> 5, lane2 = tid & 31;
            int c0 = ct8 * 8, d0 = lane2 * 4;
            float av[8][4] = {}, ak[8][4] = {};
            int jmax = c0 + 8;
            for (int j = 0; j < jmax; j++) {
                float4 vv = *(float4*)&vb_s[j*SW + d0];
                float4 kk = *(float4*)&k_s [j*SW + d0];
                float kb = kbe2[h2][j];
                kk.x *= kb; kk.y *= kb; kk.z *= kb; kk.w *= kb;
#pragma unroll
                for (int ci = 0; ci < 8; ci++) {
                    float t = T_s[(c0+ci)*65 + j];
                    av[ci][0] += t*vv.x; av[ci][1] += t*vv.y; av[ci][2] += t*vv.z; av[ci][3] += t*vv.w;
                    ak[ci][0] += t*kk.x; ak[ci][1] += t*kk.y; ak[ci][2] += t*kk.z; ak[ci][3] += t*kk.w;
                }
            }
            size_t kcd_off = gb_off * DKd;
#pragma unroll
            for (int ci = 0; ci < 8; ci++) {
                *(float4*)&g_vadj[v_off + (size_t)(c0+ci)*128 + d0] =
                    make_float4(av[ci][0], av[ci][1], av[ci][2], av[ci][3]);
                __half2 h0 = __floats2half2_rn(-ak[ci][0], -ak[ci][1]);
                __half2 h1 = __floats2half2_rn(-ak[ci][2], -ak[ci][3]);
                uint2 u; u.x = *(uint32_t*)&h0; u.y = *(uint32_t*)&h1;
                *(uint2*)&g_kcd16[kcd_off + (size_t)(c0+ci)*128 + d0] = u;
            }
        }
        __syncthreads();
    }
}

// ======== HMMA scan: fp16 operand tiles cp.async-prefetched (double buffered) ========
__global__ void __launch_bounds__(512, 1) scan_kernel() {
    extern __shared__ char smraw[];
    float*  stT  = (float*)smraw;                      // [64][STF] fp32
    __half* st16 = (__half*)(stT + 64*STF);            // [64][SH6]
    __half* vnT16= st16 + 64*SH6;                      // [64][SH7]
    __half* vkT16= vnT16 + 64*SH7;                     // [64][SH7]
    __half* q16b = vkT16 + 64*SH7;                     // [2][64][SH6]
    __half* kcdb = q16b + 2*64*SH6;                    // [2][64][SH6]
    __half* ktb  = kcdb + 2*64*SH6;                    // [2][128][SH7]
    __half* atb  = ktb + 2*128*SH7;                    // [2][64][SH7]
    __shared__ float eg_s[64], ek_s[64];

    int bh = blockIdx.x, dvt = blockIdx.y;
    int b = bh >> 5, h = bh & 31, hq = h >> 1;
    int tid = threadIdx.x, lane = tid & 31, wid = tid >> 5;

    int mW = (wid >> 2) * 16;
    int nW = (wid & 3) * 16;
    int g = lane >> 3, lr = lane & 7;
    int rr = lane >> 2, cc = (lane & 3) * 2;

    for (int i = tid; i < 64*STF; i += 512) stT[i] = 0.f;
    for (int i = tid; i < 64*SH6; i += 512) st16[i] = __float2half(0.f);

    uint32_t sQ[2]   = { smem_u32(q16b), smem_u32(q16b + 64*SH6) };
    uint32_t sKCD[2] = { smem_u32(kcdb), smem_u32(kcdb + 64*SH6) };
    uint32_t sKT[2]  = { smem_u32(ktb),  smem_u32(ktb + 128*SH7) };
    uint32_t sAT[2]  = { smem_u32(atb),  smem_u32(atb + 64*SH7) };

    uint32_t aQb[2], aKCDb[2], aATb[2];
#pragma unroll
    for (int i = 0; i < 2; i++) {
        aQb[i]   = sQ[i]   + 2u*((mW + (g&1)*8 + lr)*SH6 + (g>>1)*8);
        aKCDb[i] = sKCD[i] + 2u*((mW + (g&1)*8 + lr)*SH6 + (g>>1)*8);
        aATb[i]  = sAT[i]  + 2u*((mW + (g&1)*8 + lr)*SH7 + (g>>1)*8);
    }
    uint32_t bST = smem_u32(st16)  + 2u*((nW + (g>>1)*8 + lr)*SH6 + (g&1)*8);
    uint32_t bVN = smem_u32(vnT16) + 2u*((nW + (g>>1)*8 + lr)*SH7 + (g&1)*8);

    auto prefetch = [&](int m, int bufi) {
        if (m < NCH) {
            size_t qb = (((size_t)b*HKq + hq)*S_ + (size_t)m*CHUNK) * DKd;
            size_t cb = (((size_t)b*HVv + h )*S_ + (size_t)m*CHUNK) * DKd;
            size_t kb = (((size_t)b*HKq + hq)*(size_t)NCH + m) * (size_t)(128*64);
            size_t ab = (((size_t)b*HVv + h )*S_ + (size_t)m*CHUNK) * CHUNK;
#pragma unroll
            for (int i = 0; i < 2; i++) {
                int idx = i*512 + tid;
                int r = idx >> 4, c = (idx & 15) * 8;
                uint32_t dq = sQ[bufi] + (uint32_t)(r*SH6 + c)*2;
                asm volatile("cp.async.cg.shared.global [%0], [%1], 16;"
                             :: "r"(dq), "l"(g_q16 + qb + (size_t)r*128 + c));
                uint32_t dc = sKCD[bufi] + (uint32_t)(r*SH6 + c)*2;
                asm volatile("cp.async.cg.shared.global [%0], [%1], 16;"
                             :: "r"(dc), "l"(g_kcd16 + cb + (size_t)r*128 + c));
                int r2 = idx >> 3, c2 = (idx & 7) * 8;
                uint32_t dk2 = sKT[bufi] + (uint32_t)(r2*SH7 + c2)*2;
                asm volatile("cp.async.cg.shared.global [%0], [%1], 16;"
                             :: "r"(dk2), "l"(g_kT16 + kb + (size_t)r2*64 + c2));
            }
            {
                int r = tid >> 3, c = (tid & 7) * 8;
                uint32_t da = sAT[bufi] + (uint32_t)(r*SH7 + c)*2;
                asm volatile("cp.async.cg.shared.global [%0], [%1], 16;"
                             :: "r"(da), "l"(g_attn16 + ab + (size_t)r*64 + c));
            }
        }
        asm volatile("cp.async.commit_group;" ::: "memory");
    };

    prefetch(0, 0);
    prefetch(1, 1);

    for (int n = 0; n < NCH; n++) {
        int buf = n & 1;
        size_t kv_off = (((size_t)b*HVv + h)*S_ + (size_t)n*CHUNK) * DKd;
        size_t gb_off = ((size_t)b*HVv + h)*S_ + (size_t)n*CHUNK;

        asm volatile("cp.async.wait_group 1;" ::: "memory");
        __syncthreads();                                       // (a)
        if (tid < 64) {
            float gv = g_gc[gb_off + tid];
            float gl = g_gc[gb_off + 63];
            eg_s[tid] = expf(gv);
            ek_s[tid] = expf(gl - gv);
        }
        __syncthreads();                                       // (b)

        // ---- M1: vnew[c,dv] = vadj + (-kcd) @ state ----
        float c0[4], c1[4];
        {
            size_t vb = kv_off + (size_t)(mW + rr)*128 + dvt*64 + nW + cc;
            float2 t;
            t = *(const float2*)&g_vadj[vb];              c0[0]=t.x; c0[1]=t.y;
            t = *(const float2*)&g_vadj[vb + 8*128];      c0[2]=t.x; c0[3]=t.y;
            t = *(const float2*)&g_vadj[vb + 8];          c1[0]=t.x; c1[1]=t.y;
            t = *(const float2*)&g_vadj[vb + 8*128 + 8];  c1[2]=t.x; c1[3]=t.y;
        }
#pragma unroll
        for (int kt = 0; kt < 8; kt++) {
            uint32_t af[4], bf[4];
            ldmx4(af, aKCDb[buf] + 2u*(kt*16));
            ldmx4(bf, bST + 2u*(kt*16));
            mma_f16(c0, af, bf);
            mma_f16(c1, af, bf + 2);
        }
        {
            int cr0 = mW + rr, cr1 = mW + rr + 8;
            int d0 = nW + cc, d1 = nW + 8 + cc;
            float e0 = ek_s[cr0], e1 = ek_s[cr1];
            vnT16[(d0  )*SH7 + cr0] = __float2half_rn(c0[0]);
            vnT16[(d0+1)*SH7 + cr0] = __float2half_rn(c0[1]);
            vnT16[(d0  )*SH7 + cr1] = __float2half_rn(c0[2]);
            vnT16[(d0+1)*SH7 + cr1] = __float2half_rn(c0[3]);
            vnT16[(d1  )*SH7 + cr0] = __float2half_rn(c1[0]);
            vnT16[(d1+1)*SH7 + cr0] = __float2half_rn(c1[1]);
            vnT16[(d1  )*SH7 + cr1] = __float2half_rn(c1[2]);
            vnT16[(d1+1)*SH7 + cr1] = __float2half_rn(c1[3]);
            vkT16[(d0  )*SH7 + cr0] = __float2half_rn(c0[0]*e0);
            vkT16[(d0+1)*SH7 + cr0] = __float2half_rn(c0[1]*e0);
            vkT16[(d0  )*SH7 + cr1] = __float2half_rn(c0[2]*e1);
            vkT16[(d0+1)*SH7 + cr1] = __float2half_rn(c0[3]*e1);
            vkT16[(d1  )*SH7 + cr0] = __float2half_rn(c1[0]*e0);
            vkT16[(d1+1)*SH7 + cr0] = __float2half_rn(c1[1]*e0);
            vkT16[(d1  )*SH7 + cr1] = __float2half_rn(c1[2]*e1);
            vkT16[(d1+1)*SH7 + cr1] = __float2half_rn(c1[3]*e1);
        }
        __syncthreads();                                       // (c)

        // ---- M2: o = eg[c]*(q@state) + attn@vnew ----
        float o0[4] = {0,0,0,0}, o1[4] = {0,0,0,0};
#pragma unroll
        for (int kt = 0; kt < 8; kt++) {
            uint32_t af[4], bf[4];
            ldmx4(af, aQb[buf] + 2u*(kt*16));
            ldmx4(bf, bST + 2u*(kt*16));
            mma_f16(o0, af, bf);
            mma_f16(o1, af, bf + 2);
        }
        {
            float e0 = eg_s[mW + rr], e1 = eg_s[mW + rr + 8];
            o0[0]*=e0; o0[1]*=e0; o0[2]*=e1; o0[3]*=e1;
            o1[0]*=e0; o1[1]*=e0; o1[2]*=e1; o1[3]*=e1;
        }
#pragma unroll
        for (int kt = 0; kt < 4; kt++) {
            uint32_t af[4], bf[4];
            ldmx4(af, aATb[buf] + 2u*(kt*16));
            ldmx4(bf, bVN + 2u*(kt*16));
            mma_f16(o0, af, bf);
            mma_f16(o1, af, bf + 2);
        }
        {
            size_t ob = ((size_t)b*S_ + (size_t)n*CHUNK + mW + rr)*VALUE_DIM
                      + (size_t)h*DVd + dvt*64 + nW + cc;
            *(float2*)&g_o[ob]                       = make_float2(o0[0], o0[1]);
            *(float2*)&g_o[ob + 8*(size_t)VALUE_DIM] = make_float2(o0[2], o0[3]);
            *(float2*)&g_o[ob + 8]                   = make_float2(o1[0], o1[1]);
            *(float2*)&g_o[ob + 8*(size_t)VALUE_DIM + 8] = make_float2(o1[2], o1[3]);
        }
        __syncthreads();                                       // (d)

        // ---- M3: state_T[dv,dk] = egl*state_T + vek^T @ k ----
        float egl = eg_s[63];
#pragma unroll
        for (int i = 0; i < 2; i++) {
            int t = wid * 2 + i;
            int dv0 = (t >> 3) * 16, dk0 = (t & 7) * 16;
            float s0[4], s1[4];
            float* sp  = &stT[(dv0 + rr)*STF + dk0 + cc];
            float* sp8 = &stT[(dv0 + rr + 8)*STF + dk0 + cc];
            s0[0] = sp[0]*egl;  s0[1] = sp[1]*egl;
            s1[0] = sp[8]*egl;  s1[1] = sp[9]*egl;
            s0[2] = sp8[0]*egl; s0[3] = sp8[1]*egl;
            s1[2] = sp8[8]*egl; s1[3] = sp8[9]*egl;
            uint32_t aV = smem_u32(vkT16) + 2u*((dv0 + (g&1)*8 + lr)*SH7 + (g>>1)*8);
            uint32_t bK = sKT[buf] + 2u*((dk0 + (g>>1)*8 + lr)*SH7 + (g&1)*8);
#pragma unroll
            for (int kt = 0; kt < 4; kt++) {
                uint32_t af[4], bf[4];
                ldmx4(af, aV + 2u*(kt*16));
                ldmx4(bf, bK + 2u*(kt*16));
                mma_f16(s0, af, bf);
                mma_f16(s1, af, bf + 2);
            }
            sp[0]=s0[0];  sp[1]=s0[1];  sp[8]=s1[0];  sp[9]=s1[1];
            sp8[0]=s0[2]; sp8[1]=s0[3]; sp8[8]=s1[2]; sp8[9]=s1[3];
            *(__half2*)&st16[(dv0+rr)*SH6 + dk0 + cc]       = __floats2half2_rn(s0[0], s0[1]);
            *(__half2*)&st16[(dv0+rr)*SH6 + dk0 + 8 + cc]   = __floats2half2_rn(s1[0], s1[1]);
            *(__half2*)&st16[(dv0+rr+8)*SH6 + dk0 + cc]     = __floats2half2_rn(s0[2], s0[3]);
            *(__half2*)&st16[(dv0+rr+8)*SH6 + dk0 + 8 + cc] = __floats2half2_rn(s1[2], s1[3]);
        }
        __syncthreads();                                       // (e) — buf reads done
        prefetch(n + 2, buf);
    }
}

// -------- gated RMSNorm -> fp16 directly into GEMM2 A buffer --------
__global__ void gated_norm(const float* __restrict__ nw) {
    int bs = blockIdx.x;
    int warp = threadIdx.x >> 5, lane = threadIdx.x & 31;
    for (int h = warp; h < HVv; h += 8) {
        size_t off = (size_t)bs * VALUE_DIM + (size_t)h * DVd;
        float4 v = ((float4*)(g_o + off))[lane];
        float ss = v.x*v.x + v.y*v.y + v.z*v.z + v.w*v.w;
#pragma unroll
        for (int o = 16; o; o >>= 1) ss += __shfl_xor_sync(~0u, ss, o);
        float r = rsqrtf(ss / 128.f + 1e-6f);
        size_t zoff = (size_t)bs * QKVZ_N + 2*KEY_DIM + VALUE_DIM + (size_t)h * DVd;
        float4 z = ((const float4*)(g_qkvz + zoff))[lane];
        float4 w = ((const float4*)nw)[lane];
        float r0 = v.x * r * w.x * (z.x / (1.f + expf(-z.x)));
        float r1 = v.y * r * w.y * (z.y / (1.f + expf(-z.y)));
        float r2 = v.z * r * w.z * (z.z / (1.f + expf(-z.z)));
        float r3 = v.w * r * w.w * (z.w / (1.f + expf(-z.w)));
        __half2 h0 = __floats2half2_rn(r0, r1);
        __half2 h1 = __floats2half2_rn(r2, r3);
        uint2 hv; hv.x = *(uint32_t*)&h0; hv.y = *(uint32_t*)&h1;
        ((uint2*)(g_r + off))[lane] = hv;
    }
}

// ---------------- launcher (single stream) ----------------
extern "C" void kernel_launch(void* const* d_in, const int* in_sizes, int n_in,
                              void* d_out, int out_size) {
    const float* hidden = (const float*)d_in[0];
    const float* Wqkvz  = (const float*)d_in[1];
    const float* Wba    = (const float*)d_in[2];
    const float* convw  = (const float*)d_in[3];
    const float* dtb    = (const float*)d_in[4];
    const float* Alog   = (const float*)d_in[5];
    const float* nw     = (const float*)d_in[6];
    const float* Wout   = (const float*)d_in[7];
    float* out = (float*)d_out;

    float *qkvz_p;
    __half *p_p, *r_p, *wba_p;
    cudaGetSymbolAddress((void**)&qkvz_p, g_qkvz);
    cudaGetSymbolAddress((void**)&p_p, g_p);
    cudaGetSymbolAddress((void**)&r_p, g_r);
    cudaGetSymbolAddress((void**)&wba_p, g_wba);

    const int SMEM3 = (2*64*SW + 2*4096 + 2*4096 + 2*64*65) * 4 + 2*64*SH6 * 2;
    const int SMEM4 = 64*STF*4
                    + (64*SH6 + 2*64*SH7 + 2*64*SH6*2 + 2*128*SH7 + 2*64*SH7) * 2; // 194560
    const int SMEM_MM = NSTG * STG1 * 2;
    cudaFuncSetAttribute(chunk_prep, cudaFuncAttributeMaxDynamicSharedMemorySize, SMEM3);
    cudaFuncSetAttribute(scan_kernel, cudaFuncAttributeMaxDynamicSharedMemorySize, SMEM4);
    cudaFuncSetAttribute(mmgemm, cudaFuncAttributeMaxDynamicSharedMemorySize, SMEM_MM);

    // --- operand conversions ---
    cvt_h<<<(BSz*(size_t)HID)/1024, 256>>>(hidden, p_p);
    cvt_T<<<dim3(QKVZ_N/32, HID/32), dim3(32,8)>>>(Wqkvz, r_p, HID, QKVZ_N);
    cvt_T<<<dim3(2, HID/32), dim3(32,8)>>>(Wba, wba_p, HID, 64);

    // --- GEMM1: qkvz = hidden @ W_qkvz ---
    mmgemm<<<dim3(BSz/128, QKVZ_N/128), 256, SMEM_MM>>>(p_p, r_p, qkvz_p, BSz, QKVZ_N, HID);

    // --- BA projection (HMMA) ---
    gemm_ba_h<<<BSz/32, 256>>>(p_p);

    // --- conv + gates, chunk prep, scan, norm ---
    conv_gate<<<BSz, 256>>>(convw, dtb, Alog);
    chunk_prep<<<B_*HKq*NCH, 256, SMEM3>>>();
    scan_kernel<<<dim3(B_*HVv, 2), 512, SMEM4>>>();
    gated_norm<<<BSz, 256>>>(nw);

    // --- GEMM2: out = o @ W_out ---
    cvt_T<<<dim3(HID/32, VALUE_DIM/32), dim3(32,8)>>>(Wout, p_p, VALUE_DIM, HID);
    mmgemm<<<dim3(BSz/128, HID/128), 256, SMEM_MM>>>(r_p, p_p, out, BSz, HID, VALUE_DIM);
}